// round 2
// baseline (speedup 1.0000x reference)
#include <cuda_runtime.h>
#include <cuda_bf16.h>
#include <math.h>

// Problem constants
#define BB   4
#define TT   2048
#define DD   1024
#define HH   16
#define HD   64
#define LAT  128
#define ROPE 32
#define ROWS (BB*TT)          // 8192
#define EPSV 1e-6f

// Scratch (static device allocations are allowed)
__device__ float g_q  [ROWS * DD];        // x@Wq                (8192,1024)
__device__ float g_qr [ROWS * HH * ROPE]; // normalized q[:, :32] per head (8192,512)
__device__ float g_kv [ROWS * LAT];       // x@Wkv               (8192,128)
__device__ float g_k  [ROWS * HH * ROPE]; // normalized k        (8192,512)
__device__ float g_v  [ROWS * HH * ROPE]; // v_c                 (8192,512)
__device__ float g_att[ROWS * HH * ROPE]; // attention out       (8192,512)
__device__ float g_wop[HH * ROPE * DD];   // packed Wo           (512,1024)

// ---------------------------------------------------------------------------
// Tiled SGEMM: C[M,N] = A[M,K] @ B[K,N], all row-major.
// BM=BN=128, BK=16, 256 threads, 8x8 per thread. Requires M%128==0, N%128==0,
// K%16==0 (all shapes here satisfy this).
// ---------------------------------------------------------------------------
__global__ __launch_bounds__(256) void sgemm_kernel(
    int M, int N, int K,
    const float* __restrict__ A, const float* __restrict__ B,
    float* __restrict__ C)
{
    __shared__ float As[16][128];
    __shared__ float Bs[16][128];

    const int tid = threadIdx.x;
    const int tx  = tid & 15;          // 0..15
    const int ty  = tid >> 4;          // 0..15
    const int aRow = tid >> 2;         // 0..63 (+64 second pass)
    const int aCol = (tid & 3) * 4;    // 0,4,8,12
    const int bRow = tid >> 5;         // 0..7  (+8 second pass)
    const int bCol = (tid & 31) * 4;   // 0..124

    const int blockM = blockIdx.y * 128;
    const int blockN = blockIdx.x * 128;

    float acc[8][8];
    #pragma unroll
    for (int i = 0; i < 8; i++)
        #pragma unroll
        for (int j = 0; j < 8; j++) acc[i][j] = 0.f;

    for (int k0 = 0; k0 < K; k0 += 16) {
        // load A tile (transposed into As[k][m])
        #pragma unroll
        for (int p = 0; p < 2; p++) {
            int r = aRow + p * 64;
            float4 av = *(const float4*)&A[(size_t)(blockM + r) * K + k0 + aCol];
            As[aCol + 0][r] = av.x;
            As[aCol + 1][r] = av.y;
            As[aCol + 2][r] = av.z;
            As[aCol + 3][r] = av.w;
        }
        // load B tile
        #pragma unroll
        for (int p = 0; p < 2; p++) {
            int r = bRow + p * 8;
            *(float4*)&Bs[r][bCol] =
                *(const float4*)&B[(size_t)(k0 + r) * N + blockN + bCol];
        }
        __syncthreads();

        #pragma unroll
        for (int kk = 0; kk < 16; kk++) {
            float a[8], b[8];
            *(float4*)&a[0] = *(const float4*)&As[kk][ty * 8 + 0];
            *(float4*)&a[4] = *(const float4*)&As[kk][ty * 8 + 4];
            *(float4*)&b[0] = *(const float4*)&Bs[kk][tx * 8 + 0];
            *(float4*)&b[4] = *(const float4*)&Bs[kk][tx * 8 + 4];
            #pragma unroll
            for (int i = 0; i < 8; i++)
                #pragma unroll
                for (int j = 0; j < 8; j++)
                    acc[i][j] += a[i] * b[j];
        }
        __syncthreads();
    }

    // store C
    const int rowC = blockM + ty * 8;
    const int colC = blockN + tx * 8;
    #pragma unroll
    for (int i = 0; i < 8; i++) {
        *(float4*)&C[(size_t)(rowC + i) * N + colC + 0] = *(float4*)&acc[i][0];
        *(float4*)&C[(size_t)(rowC + i) * N + colC + 4] = *(float4*)&acc[i][4];
    }
}

// ---------------------------------------------------------------------------
// Pack Wo: WoP[h*32+d][:] = Wo[h*64+d][:]   (only first 32 dims per head used)
// ---------------------------------------------------------------------------
__global__ void pack_wo_kernel(const float* __restrict__ Wo, float* __restrict__ WoP)
{
    int idx = blockIdx.x * blockDim.x + threadIdx.x;   // over 512*1024
    if (idx >= HH * ROPE * DD) return;
    int r = idx >> 10;          // 0..511
    int n = idx & 1023;
    int h = r >> 5;
    int d = r & 31;
    WoP[idx] = Wo[(size_t)(h * HD + d) * DD + n];
}

// ---------------------------------------------------------------------------
// Q RMSNorm: per (row, head), rms over all 64 dims, write first 32 normalized.
// One warp per (row, head).
// ---------------------------------------------------------------------------
__global__ void qnorm_kernel(const float* __restrict__ q,
                             const float* __restrict__ qg,
                             float* __restrict__ qr)
{
    int warp = (blockIdx.x * blockDim.x + threadIdx.x) >> 5;
    int lane = threadIdx.x & 31;
    if (warp >= ROWS * HH) return;
    int row = warp >> 4;
    int h   = warp & 15;
    const float* base = q + (size_t)row * DD + h * HD;
    float v0 = base[lane];
    float v1 = base[lane + 32];
    float ss = v0 * v0 + v1 * v1;
    #pragma unroll
    for (int o = 16; o > 0; o >>= 1) ss += __shfl_xor_sync(0xffffffffu, ss, o);
    float rinv = rsqrtf(ss * (1.0f / HD) + EPSV);
    qr[(size_t)row * (HH * ROPE) + h * ROPE + lane] = qg[lane] * v0 * rinv;
}

// ---------------------------------------------------------------------------
// K RMSNorm: per (row, head) over 32 dims, in place. One warp per (row, head).
// ---------------------------------------------------------------------------
__global__ void knorm_kernel(float* __restrict__ k, const float* __restrict__ kg)
{
    int warp = (blockIdx.x * blockDim.x + threadIdx.x) >> 5;
    int lane = threadIdx.x & 31;
    if (warp >= ROWS * HH) return;
    float* base = k + (size_t)warp * ROPE;
    float v = base[lane];
    float ss = v * v;
    #pragma unroll
    for (int o = 16; o > 0; o >>= 1) ss += __shfl_xor_sync(0xffffffffu, ss, o);
    float rinv = rsqrtf(ss * (1.0f / ROPE) + EPSV);
    base[lane] = kg[lane] * v * rinv;
}

// ---------------------------------------------------------------------------
// Flash attention (causal), head_dim 32 for both K and V.
// Grid: (T/64, B*H). 64 threads; thread tid owns query t = qt*64+tid.
// K/V tiles staged in smem; all threads iterate keys in lockstep so smem
// reads are broadcasts (no bank conflicts).
// ---------------------------------------------------------------------------
#define BQ 64
#define BKT 64
__global__ __launch_bounds__(64) void attn_kernel(
    const float* __restrict__ qr, const float* __restrict__ kk,
    const float* __restrict__ vv, float* __restrict__ att)
{
    __shared__ float Qs[BQ][36];
    __shared__ float Ks[BKT][32];
    __shared__ float Vs[BKT][32];

    const int qt  = blockIdx.x;
    const int bh  = blockIdx.y;
    const int b   = bh >> 4;
    const int h   = bh & 15;
    const int tid = threadIdx.x;
    const int t   = qt * BQ + tid;
    const int rbase = b * TT;
    const int W = HH * ROPE;   // 512

    // stage Q tile (coalesced), then copy own row to registers
    for (int f = tid; f < BQ * 8; f += 64) {
        int row = f >> 3, c4 = (f & 7) * 4;
        const float* src = &qr[(size_t)(rbase + qt * BQ + row) * W + h * ROPE + c4];
        Qs[row][c4 + 0] = src[0];
        Qs[row][c4 + 1] = src[1];
        Qs[row][c4 + 2] = src[2];
        Qs[row][c4 + 3] = src[3];
    }
    __syncthreads();

    float qreg[32];
    #pragma unroll
    for (int d = 0; d < 32; d++) qreg[d] = Qs[tid][d];

    float m = -INFINITY, l = 0.f;
    float acc[32];
    #pragma unroll
    for (int d = 0; d < 32; d++) acc[d] = 0.f;

    for (int kt = 0; kt <= qt; kt++) {
        // load K/V tile
        for (int f = tid; f < BKT * 8; f += 64) {
            int row = f >> 3, c4 = (f & 7) * 4;
            size_t g = (size_t)(rbase + kt * BKT + row) * W + h * ROPE + c4;
            *(float4*)&Ks[row][c4] = *(const float4*)&kk[g];
            *(float4*)&Vs[row][c4] = *(const float4*)&vv[g];
        }
        __syncthreads();

        const int klim = (kt == qt) ? tid : (BKT - 1); // max valid local key

        for (int c = 0; c < BKT; c += 16) {
            float s16[16];
            float mx = m;
            #pragma unroll
            for (int j = 0; j < 16; j++) {
                int key = c + j;
                float s = 0.f;
                #pragma unroll
                for (int d = 0; d < 32; d++) s += qreg[d] * Ks[key][d];
                s *= 0.125f;                       // 1/sqrt(64)
                if (key > klim) s = -INFINITY;
                s16[j] = s;
                mx = fmaxf(mx, s);
            }
            float scale = __expf(m - mx);
            l *= scale;
            #pragma unroll
            for (int d = 0; d < 32; d++) acc[d] *= scale;
            #pragma unroll
            for (int j = 0; j < 16; j++) {
                float p = __expf(s16[j] - mx);
                l += p;
                #pragma unroll
                for (int d = 0; d < 32; d++) acc[d] += p * Vs[c + j][d];
            }
            m = mx;
        }
        __syncthreads();
    }

    float inv = 1.0f / l;
    float* dst = &att[(size_t)(rbase + t) * W + h * ROPE];
    #pragma unroll
    for (int d = 0; d < 32; d++) dst[d] = acc[d] * inv;
}

// ---------------------------------------------------------------------------
// Launch
// ---------------------------------------------------------------------------
extern "C" void kernel_launch(void* const* d_in, const int* in_sizes, int n_in,
                              void* d_out, int out_size)
{
    const float* x   = (const float*)d_in[0];
    const float* Wq  = (const float*)d_in[1];
    const float* Wkv = (const float*)d_in[2];
    const float* Wk  = (const float*)d_in[3];
    const float* Wv  = (const float*)d_in[4];
    const float* Wo  = (const float*)d_in[5];
    const float* qg  = (const float*)d_in[6];
    const float* kg  = (const float*)d_in[7];
    float* out = (float*)d_out;

    float *pq, *pqr, *pkv, *pk, *pv, *patt, *pwop;
    cudaGetSymbolAddress((void**)&pq,   g_q);
    cudaGetSymbolAddress((void**)&pqr,  g_qr);
    cudaGetSymbolAddress((void**)&pkv,  g_kv);
    cudaGetSymbolAddress((void**)&pk,   g_k);
    cudaGetSymbolAddress((void**)&pv,   g_v);
    cudaGetSymbolAddress((void**)&patt, g_att);
    cudaGetSymbolAddress((void**)&pwop, g_wop);

    // pack Wo (512x1024)
    pack_wo_kernel<<<(HH * ROPE * DD + 255) / 256, 256>>>(Wo, pwop);

    // q = x @ Wq   (8192,1024,1024)
    sgemm_kernel<<<dim3(DD / 128, ROWS / 128), 256>>>(ROWS, DD, DD, x, Wq, pq);
    // kv = x @ Wkv (8192,128,1024)
    sgemm_kernel<<<dim3(LAT / 128, ROWS / 128), 256>>>(ROWS, LAT, DD, x, Wkv, pkv);

    // q norm -> qr
    {
        int warps = ROWS * HH;
        qnorm_kernel<<<(warps * 32 + 127) / 128, 128>>>(pq, qg, pqr);
    }

    // k = kv @ Wk (8192,512,128) ; v = kv @ Wv
    sgemm_kernel<<<dim3((HH * ROPE) / 128, ROWS / 128), 256>>>(ROWS, HH * ROPE, LAT, pkv, Wk, pk);
    sgemm_kernel<<<dim3((HH * ROPE) / 128, ROWS / 128), 256>>>(ROWS, HH * ROPE, LAT, pkv, Wv, pv);

    // k norm in-place
    {
        int warps = ROWS * HH;
        knorm_kernel<<<(warps * 32 + 127) / 128, 128>>>(pk, kg);
    }

    // attention
    attn_kernel<<<dim3(TT / BQ, BB * HH), 64>>>(pqr, pk, pv, patt);

    // out = att @ WoP  (8192,1024,512)
    sgemm_kernel<<<dim3(DD / 128, ROWS / 128), 256>>>(ROWS, DD, HH * ROPE, patt, pwop, out);
}

// round 3
// speedup vs baseline: 1.0012x; 1.0012x over previous
#include <cuda_runtime.h>
#include <cuda_bf16.h>
#include <math.h>

// Problem constants
#define BB   4
#define TT   2048
#define DD   1024
#define HH   16
#define HD   64
#define LAT  128
#define ROPE 32
#define ROWS (BB*TT)          // 8192
#define EPSV 1e-6f

// Scratch (static device allocations are allowed)
__device__ float g_q  [ROWS * DD];        // x@Wq                (8192,1024)
__device__ float g_qr [ROWS * HH * ROPE]; // normalized q[:, :32] per head (8192,512)
__device__ float g_kv [ROWS * LAT];       // x@Wkv               (8192,128)
__device__ float g_k  [ROWS * HH * ROPE]; // normalized k        (8192,512)
__device__ float g_v  [ROWS * HH * ROPE]; // v_c                 (8192,512)
__device__ float g_att[ROWS * HH * ROPE]; // attention out       (8192,512)
__device__ float g_wop[HH * ROPE * DD];   // packed Wo           (512,1024)

// ---------------------------------------------------------------------------
// Tiled SGEMM: C[M,N] = A[M,K] @ B[K,N], all row-major.
// BM=BN=128, BK=16, 256 threads, 8x8 per thread. Requires M%128==0, N%128==0,
// K%16==0 (all shapes here satisfy this).
// ---------------------------------------------------------------------------
__global__ __launch_bounds__(256) void sgemm_kernel(
    int M, int N, int K,
    const float* __restrict__ A, const float* __restrict__ B,
    float* __restrict__ C)
{
    __shared__ float As[16][128];
    __shared__ float Bs[16][128];

    const int tid = threadIdx.x;
    const int tx  = tid & 15;          // 0..15
    const int ty  = tid >> 4;          // 0..15
    const int aRow = tid >> 2;         // 0..63 (+64 second pass)
    const int aCol = (tid & 3) * 4;    // 0,4,8,12
    const int bRow = tid >> 5;         // 0..7  (+8 second pass)
    const int bCol = (tid & 31) * 4;   // 0..124

    const int blockM = blockIdx.y * 128;
    const int blockN = blockIdx.x * 128;

    float acc[8][8];
    #pragma unroll
    for (int i = 0; i < 8; i++)
        #pragma unroll
        for (int j = 0; j < 8; j++) acc[i][j] = 0.f;

    for (int k0 = 0; k0 < K; k0 += 16) {
        // load A tile (transposed into As[k][m])
        #pragma unroll
        for (int p = 0; p < 2; p++) {
            int r = aRow + p * 64;
            float4 av = *(const float4*)&A[(size_t)(blockM + r) * K + k0 + aCol];
            As[aCol + 0][r] = av.x;
            As[aCol + 1][r] = av.y;
            As[aCol + 2][r] = av.z;
            As[aCol + 3][r] = av.w;
        }
        // load B tile
        #pragma unroll
        for (int p = 0; p < 2; p++) {
            int r = bRow + p * 8;
            *(float4*)&Bs[r][bCol] =
                *(const float4*)&B[(size_t)(k0 + r) * N + blockN + bCol];
        }
        __syncthreads();

        #pragma unroll
        for (int kk = 0; kk < 16; kk++) {
            float a[8], b[8];
            *(float4*)&a[0] = *(const float4*)&As[kk][ty * 8 + 0];
            *(float4*)&a[4] = *(const float4*)&As[kk][ty * 8 + 4];
            *(float4*)&b[0] = *(const float4*)&Bs[kk][tx * 8 + 0];
            *(float4*)&b[4] = *(const float4*)&Bs[kk][tx * 8 + 4];
            #pragma unroll
            for (int i = 0; i < 8; i++)
                #pragma unroll
                for (int j = 0; j < 8; j++)
                    acc[i][j] += a[i] * b[j];
        }
        __syncthreads();
    }

    // store C
    const int rowC = blockM + ty * 8;
    const int colC = blockN + tx * 8;
    #pragma unroll
    for (int i = 0; i < 8; i++) {
        *(float4*)&C[(size_t)(rowC + i) * N + colC + 0] = *(float4*)&acc[i][0];
        *(float4*)&C[(size_t)(rowC + i) * N + colC + 4] = *(float4*)&acc[i][4];
    }
}

// ---------------------------------------------------------------------------
// Pack Wo: WoP[h*32+d][:] = Wo[h*64+d][:]   (only first 32 dims per head used)
// ---------------------------------------------------------------------------
__global__ void pack_wo_kernel(const float* __restrict__ Wo, float* __restrict__ WoP)
{
    int idx = blockIdx.x * blockDim.x + threadIdx.x;   // over 512*1024
    if (idx >= HH * ROPE * DD) return;
    int r = idx >> 10;          // 0..511
    int n = idx & 1023;
    int h = r >> 5;
    int d = r & 31;
    WoP[idx] = Wo[(size_t)(h * HD + d) * DD + n];
}

// ---------------------------------------------------------------------------
// Q RMSNorm: per (row, head), rms over all 64 dims, write first 32 normalized.
// One warp per (row, head).
// ---------------------------------------------------------------------------
__global__ void qnorm_kernel(const float* __restrict__ q,
                             const float* __restrict__ qg,
                             float* __restrict__ qr)
{
    int warp = (blockIdx.x * blockDim.x + threadIdx.x) >> 5;
    int lane = threadIdx.x & 31;
    if (warp >= ROWS * HH) return;
    int row = warp >> 4;
    int h   = warp & 15;
    const float* base = q + (size_t)row * DD + h * HD;
    float v0 = base[lane];
    float v1 = base[lane + 32];
    float ss = v0 * v0 + v1 * v1;
    #pragma unroll
    for (int o = 16; o > 0; o >>= 1) ss += __shfl_xor_sync(0xffffffffu, ss, o);
    float rinv = rsqrtf(ss * (1.0f / HD) + EPSV);
    qr[(size_t)row * (HH * ROPE) + h * ROPE + lane] = qg[lane] * v0 * rinv;
}

// ---------------------------------------------------------------------------
// K RMSNorm: per (row, head) over 32 dims, in place. One warp per (row, head).
// ---------------------------------------------------------------------------
__global__ void knorm_kernel(float* __restrict__ k, const float* __restrict__ kg)
{
    int warp = (blockIdx.x * blockDim.x + threadIdx.x) >> 5;
    int lane = threadIdx.x & 31;
    if (warp >= ROWS * HH) return;
    float* base = k + (size_t)warp * ROPE;
    float v = base[lane];
    float ss = v * v;
    #pragma unroll
    for (int o = 16; o > 0; o >>= 1) ss += __shfl_xor_sync(0xffffffffu, ss, o);
    float rinv = rsqrtf(ss * (1.0f / ROPE) + EPSV);
    base[lane] = kg[lane] * v * rinv;
}

// ---------------------------------------------------------------------------
// Flash attention (causal), head_dim 32 for both K and V.
// Grid: (T/64, B*H). 64 threads; thread tid owns query t = qt*64+tid.
// K/V tiles staged in smem; all threads iterate keys in lockstep so smem
// reads are broadcasts (no bank conflicts).
// ---------------------------------------------------------------------------
#define BQ 64
#define BKT 64
__global__ __launch_bounds__(64) void attn_kernel(
    const float* __restrict__ qr, const float* __restrict__ kk,
    const float* __restrict__ vv, float* __restrict__ att)
{
    __shared__ float Qs[BQ][36];
    __shared__ float Ks[BKT][32];
    __shared__ float Vs[BKT][32];

    const int qt  = blockIdx.x;
    const int bh  = blockIdx.y;
    const int b   = bh >> 4;
    const int h   = bh & 15;
    const int tid = threadIdx.x;
    const int t   = qt * BQ + tid;
    const int rbase = b * TT;
    const int W = HH * ROPE;   // 512

    // stage Q tile (coalesced), then copy own row to registers
    for (int f = tid; f < BQ * 8; f += 64) {
        int row = f >> 3, c4 = (f & 7) * 4;
        const float* src = &qr[(size_t)(rbase + qt * BQ + row) * W + h * ROPE + c4];
        Qs[row][c4 + 0] = src[0];
        Qs[row][c4 + 1] = src[1];
        Qs[row][c4 + 2] = src[2];
        Qs[row][c4 + 3] = src[3];
    }
    __syncthreads();

    float qreg[32];
    #pragma unroll
    for (int d = 0; d < 32; d++) qreg[d] = Qs[tid][d];

    float m = -INFINITY, l = 0.f;
    float acc[32];
    #pragma unroll
    for (int d = 0; d < 32; d++) acc[d] = 0.f;

    for (int kt = 0; kt <= qt; kt++) {
        // load K/V tile
        for (int f = tid; f < BKT * 8; f += 64) {
            int row = f >> 3, c4 = (f & 7) * 4;
            size_t g = (size_t)(rbase + kt * BKT + row) * W + h * ROPE + c4;
            *(float4*)&Ks[row][c4] = *(const float4*)&kk[g];
            *(float4*)&Vs[row][c4] = *(const float4*)&vv[g];
        }
        __syncthreads();

        const int klim = (kt == qt) ? tid : (BKT - 1); // max valid local key

        for (int c = 0; c < BKT; c += 16) {
            float s16[16];
            float mx = m;
            #pragma unroll
            for (int j = 0; j < 16; j++) {
                int key = c + j;
                float s = 0.f;
                #pragma unroll
                for (int d = 0; d < 32; d++) s += qreg[d] * Ks[key][d];
                s *= 0.125f;                       // 1/sqrt(64)
                if (key > klim) s = -INFINITY;
                s16[j] = s;
                mx = fmaxf(mx, s);
            }
            float scale = __expf(m - mx);
            l *= scale;
            #pragma unroll
            for (int d = 0; d < 32; d++) acc[d] *= scale;
            #pragma unroll
            for (int j = 0; j < 16; j++) {
                float p = __expf(s16[j] - mx);
                l += p;
                #pragma unroll
                for (int d = 0; d < 32; d++) acc[d] += p * Vs[c + j][d];
            }
            m = mx;
        }
        __syncthreads();
    }

    float inv = 1.0f / l;
    float* dst = &att[(size_t)(rbase + t) * W + h * ROPE];
    #pragma unroll
    for (int d = 0; d < 32; d++) dst[d] = acc[d] * inv;
}

// ---------------------------------------------------------------------------
// Launch
// ---------------------------------------------------------------------------
extern "C" void kernel_launch(void* const* d_in, const int* in_sizes, int n_in,
                              void* d_out, int out_size)
{
    const float* x   = (const float*)d_in[0];
    const float* Wq  = (const float*)d_in[1];
    const float* Wkv = (const float*)d_in[2];
    const float* Wk  = (const float*)d_in[3];
    const float* Wv  = (const float*)d_in[4];
    const float* Wo  = (const float*)d_in[5];
    const float* qg  = (const float*)d_in[6];
    const float* kg  = (const float*)d_in[7];
    float* out = (float*)d_out;

    float *pq, *pqr, *pkv, *pk, *pv, *patt, *pwop;
    cudaGetSymbolAddress((void**)&pq,   g_q);
    cudaGetSymbolAddress((void**)&pqr,  g_qr);
    cudaGetSymbolAddress((void**)&pkv,  g_kv);
    cudaGetSymbolAddress((void**)&pk,   g_k);
    cudaGetSymbolAddress((void**)&pv,   g_v);
    cudaGetSymbolAddress((void**)&patt, g_att);
    cudaGetSymbolAddress((void**)&pwop, g_wop);

    // pack Wo (512x1024)
    pack_wo_kernel<<<(HH * ROPE * DD + 255) / 256, 256>>>(Wo, pwop);

    // q = x @ Wq   (8192,1024,1024)
    sgemm_kernel<<<dim3(DD / 128, ROWS / 128), 256>>>(ROWS, DD, DD, x, Wq, pq);
    // kv = x @ Wkv (8192,128,1024)
    sgemm_kernel<<<dim3(LAT / 128, ROWS / 128), 256>>>(ROWS, LAT, DD, x, Wkv, pkv);

    // q norm -> qr
    {
        int warps = ROWS * HH;
        qnorm_kernel<<<(warps * 32 + 127) / 128, 128>>>(pq, qg, pqr);
    }

    // k = kv @ Wk (8192,512,128) ; v = kv @ Wv
    sgemm_kernel<<<dim3((HH * ROPE) / 128, ROWS / 128), 256>>>(ROWS, HH * ROPE, LAT, pkv, Wk, pk);
    sgemm_kernel<<<dim3((HH * ROPE) / 128, ROWS / 128), 256>>>(ROWS, HH * ROPE, LAT, pkv, Wv, pv);

    // k norm in-place
    {
        int warps = ROWS * HH;
        knorm_kernel<<<(warps * 32 + 127) / 128, 128>>>(pk, kg);
    }

    // attention
    attn_kernel<<<dim3(TT / BQ, BB * HH), 64>>>(pqr, pk, pv, patt);

    // out = att @ WoP  (8192,1024,512)
    sgemm_kernel<<<dim3(DD / 128, ROWS / 128), 256>>>(ROWS, DD, HH * ROPE, patt, pwop, out);
}

// round 4
// speedup vs baseline: 1.4495x; 1.4478x over previous
#include <cuda_runtime.h>
#include <cuda_bf16.h>
#include <math.h>

// Problem constants
#define BB   4
#define TT   2048
#define DD   1024
#define HH   16
#define HD   64
#define LAT  128
#define ROPE 32
#define ROWS (BB*TT)          // 8192
#define EPSV 1e-6f

// Scratch
__device__ float g_q  [ROWS * DD];
__device__ float g_qr [ROWS * HH * ROPE];
__device__ float g_kv [ROWS * LAT];
__device__ float g_k  [ROWS * HH * ROPE];
__device__ float g_v  [ROWS * HH * ROPE];
__device__ float g_att[ROWS * HH * ROPE];
__device__ float g_wop[HH * ROPE * DD];

// ---------------------------------------------------------------------------
// fp32 -> tf32 bits, round-to-nearest (unbiased; truncation would bias sums)
// ---------------------------------------------------------------------------
__device__ __forceinline__ unsigned f2tf(float f) {
    unsigned u;
    asm("cvt.rna.tf32.f32 %0, %1;" : "=r"(u) : "f"(f));
    return u;
}

// ---------------------------------------------------------------------------
// TF32 tensor-core GEMM: C[M,N] = A[M,K] @ B[K,N], row-major.
// BM=BN=128, BK=16, 256 threads = 8 warps in 2(m)x4(n); each warp 64x32
// as 4x4 tiles of mma.sync.m16n8k8.tf32. Requires M%128==0, N%128==0, K%16==0.
// ---------------------------------------------------------------------------
__global__ __launch_bounds__(256) void gemm_tf32(
    int M, int N, int K,
    const float* __restrict__ A, const float* __restrict__ B,
    float* __restrict__ C)
{
    // Padding chosen for conflict-free fragment LDS under the m16n8k8 map:
    // As row stride 20 (20%32=20 -> 20*g mod 32 distinct for g=0..7)
    // Bs row stride 136 (136%32=8 -> 8*t4+g distinct over the warp)
    __shared__ unsigned As[128][20];
    __shared__ unsigned Bs[16][136];

    const int tid  = threadIdx.x;
    const int lane = tid & 31;
    const int warp = tid >> 5;
    const int g    = lane >> 2;      // group id (0..7)
    const int t4   = lane & 3;       // thread-in-group (0..3)
    const int wr   = warp >> 2;      // warp row 0..1 (64 rows each)
    const int wc   = warp & 3;       // warp col 0..3 (32 cols each)

    const int bM = blockIdx.y * 128;
    const int bN = blockIdx.x * 128;

    const int aRow = tid >> 2;           // 0..63 (+64)
    const int aCol = (tid & 3) * 4;      // 0,4,8,12
    const int bRow = tid >> 5;           // 0..7  (+8)
    const int bCol = (tid & 31) * 4;     // 0..124

    float acc[4][4][4];
    #pragma unroll
    for (int i = 0; i < 4; i++)
        #pragma unroll
        for (int j = 0; j < 4; j++)
            #pragma unroll
            for (int c = 0; c < 4; c++) acc[i][j][c] = 0.f;

    for (int k0 = 0; k0 < K; k0 += 16) {
        // stage A tile (row-major [m][k], tf32-converted)
        #pragma unroll
        for (int p = 0; p < 2; p++) {
            int r = aRow + p * 64;
            float4 v = *(const float4*)&A[(size_t)(bM + r) * K + k0 + aCol];
            As[r][aCol + 0] = f2tf(v.x);
            As[r][aCol + 1] = f2tf(v.y);
            As[r][aCol + 2] = f2tf(v.z);
            As[r][aCol + 3] = f2tf(v.w);
        }
        // stage B tile (row-major [k][n], tf32-converted)
        #pragma unroll
        for (int p = 0; p < 2; p++) {
            int r = bRow + p * 8;
            float4 v = *(const float4*)&B[(size_t)(k0 + r) * N + bN + bCol];
            uint4 u;
            u.x = f2tf(v.x); u.y = f2tf(v.y); u.z = f2tf(v.z); u.w = f2tf(v.w);
            *(uint4*)&Bs[r][bCol] = u;
        }
        __syncthreads();

        #pragma unroll
        for (int kk = 0; kk < 16; kk += 8) {
            unsigned a[4][4], b[4][2];
            #pragma unroll
            for (int mi = 0; mi < 4; mi++) {
                int row = wr * 64 + mi * 16 + g;
                a[mi][0] = As[row    ][kk + t4];
                a[mi][1] = As[row + 8][kk + t4];
                a[mi][2] = As[row    ][kk + t4 + 4];
                a[mi][3] = As[row + 8][kk + t4 + 4];
            }
            #pragma unroll
            for (int ni = 0; ni < 4; ni++) {
                int col = wc * 32 + ni * 8 + g;
                b[ni][0] = Bs[kk + t4    ][col];
                b[ni][1] = Bs[kk + t4 + 4][col];
            }
            #pragma unroll
            for (int mi = 0; mi < 4; mi++)
                #pragma unroll
                for (int ni = 0; ni < 4; ni++)
                    asm volatile(
                        "mma.sync.aligned.m16n8k8.row.col.f32.tf32.tf32.f32 "
                        "{%0,%1,%2,%3}, {%4,%5,%6,%7}, {%8,%9}, {%0,%1,%2,%3};"
                        : "+f"(acc[mi][ni][0]), "+f"(acc[mi][ni][1]),
                          "+f"(acc[mi][ni][2]), "+f"(acc[mi][ni][3])
                        : "r"(a[mi][0]), "r"(a[mi][1]), "r"(a[mi][2]), "r"(a[mi][3]),
                          "r"(b[ni][0]), "r"(b[ni][1]));
        }
        __syncthreads();
    }

    // epilogue: c0,c1 at (row g, cols 2*t4, 2*t4+1); c2,c3 at row g+8
    #pragma unroll
    for (int mi = 0; mi < 4; mi++) {
        #pragma unroll
        for (int ni = 0; ni < 4; ni++) {
            int row = bM + wr * 64 + mi * 16 + g;
            int col = bN + wc * 32 + ni * 8 + 2 * t4;
            float2 v0 = make_float2(acc[mi][ni][0], acc[mi][ni][1]);
            float2 v1 = make_float2(acc[mi][ni][2], acc[mi][ni][3]);
            *(float2*)&C[(size_t)row * N + col]       = v0;
            *(float2*)&C[(size_t)(row + 8) * N + col] = v1;
        }
    }
}

// ---------------------------------------------------------------------------
// Pack Wo: WoP[h*32+d][:] = Wo[h*64+d][:]
// ---------------------------------------------------------------------------
__global__ void pack_wo_kernel(const float* __restrict__ Wo, float* __restrict__ WoP)
{
    int idx = blockIdx.x * blockDim.x + threadIdx.x;
    if (idx >= HH * ROPE * DD) return;
    int r = idx >> 10;
    int n = idx & 1023;
    int h = r >> 5;
    int d = r & 31;
    WoP[idx] = Wo[(size_t)(h * HD + d) * DD + n];
}

// ---------------------------------------------------------------------------
// Q RMSNorm (rms over 64 dims, keep first 32)
// ---------------------------------------------------------------------------
__global__ void qnorm_kernel(const float* __restrict__ q,
                             const float* __restrict__ qg,
                             float* __restrict__ qr)
{
    int warp = (blockIdx.x * blockDim.x + threadIdx.x) >> 5;
    int lane = threadIdx.x & 31;
    if (warp >= ROWS * HH) return;
    int row = warp >> 4;
    int h   = warp & 15;
    const float* base = q + (size_t)row * DD + h * HD;
    float v0 = base[lane];
    float v1 = base[lane + 32];
    float ss = v0 * v0 + v1 * v1;
    #pragma unroll
    for (int o = 16; o > 0; o >>= 1) ss += __shfl_xor_sync(0xffffffffu, ss, o);
    float rinv = rsqrtf(ss * (1.0f / HD) + EPSV);
    qr[(size_t)row * (HH * ROPE) + h * ROPE + lane] = qg[lane] * v0 * rinv;
}

// ---------------------------------------------------------------------------
// K RMSNorm (32 dims, in place)
// ---------------------------------------------------------------------------
__global__ void knorm_kernel(float* __restrict__ k, const float* __restrict__ kg)
{
    int warp = (blockIdx.x * blockDim.x + threadIdx.x) >> 5;
    int lane = threadIdx.x & 31;
    if (warp >= ROWS * HH) return;
    float* base = k + (size_t)warp * ROPE;
    float v = base[lane];
    float ss = v * v;
    #pragma unroll
    for (int o = 16; o > 0; o >>= 1) ss += __shfl_xor_sync(0xffffffffu, ss, o);
    float rinv = rsqrtf(ss * (1.0f / ROPE) + EPSV);
    base[lane] = kg[lane] * v * rinv;
}

// ---------------------------------------------------------------------------
// Flash attention (causal), head_dim 32 / 32
// ---------------------------------------------------------------------------
#define BQ 64
#define BKT 64
__global__ __launch_bounds__(64) void attn_kernel(
    const float* __restrict__ qr, const float* __restrict__ kk,
    const float* __restrict__ vv, float* __restrict__ att)
{
    __shared__ float Qs[BQ][36];
    __shared__ float Ks[BKT][32];
    __shared__ float Vs[BKT][32];

    const int qt  = blockIdx.x;
    const int bh  = blockIdx.y;
    const int b   = bh >> 4;
    const int h   = bh & 15;
    const int tid = threadIdx.x;
    const int t   = qt * BQ + tid;
    const int rbase = b * TT;
    const int W = HH * ROPE;

    for (int f = tid; f < BQ * 8; f += 64) {
        int row = f >> 3, c4 = (f & 7) * 4;
        const float* src = &qr[(size_t)(rbase + qt * BQ + row) * W + h * ROPE + c4];
        Qs[row][c4 + 0] = src[0];
        Qs[row][c4 + 1] = src[1];
        Qs[row][c4 + 2] = src[2];
        Qs[row][c4 + 3] = src[3];
    }
    __syncthreads();

    float qreg[32];
    #pragma unroll
    for (int d = 0; d < 32; d++) qreg[d] = Qs[tid][d];

    float m = -INFINITY, l = 0.f;
    float acc[32];
    #pragma unroll
    for (int d = 0; d < 32; d++) acc[d] = 0.f;

    for (int kt = 0; kt <= qt; kt++) {
        for (int f = tid; f < BKT * 8; f += 64) {
            int row = f >> 3, c4 = (f & 7) * 4;
            size_t gaddr = (size_t)(rbase + kt * BKT + row) * W + h * ROPE + c4;
            *(float4*)&Ks[row][c4] = *(const float4*)&kk[gaddr];
            *(float4*)&Vs[row][c4] = *(const float4*)&vv[gaddr];
        }
        __syncthreads();

        const int klim = (kt == qt) ? tid : (BKT - 1);

        for (int c = 0; c < BKT; c += 16) {
            float s16[16];
            float mx = m;
            #pragma unroll
            for (int j = 0; j < 16; j++) {
                int key = c + j;
                float s = 0.f;
                #pragma unroll
                for (int d = 0; d < 32; d++) s += qreg[d] * Ks[key][d];
                s *= 0.125f;
                if (key > klim) s = -INFINITY;
                s16[j] = s;
                mx = fmaxf(mx, s);
            }
            float scale = __expf(m - mx);
            l *= scale;
            #pragma unroll
            for (int d = 0; d < 32; d++) acc[d] *= scale;
            #pragma unroll
            for (int j = 0; j < 16; j++) {
                float p = __expf(s16[j] - mx);
                l += p;
                #pragma unroll
                for (int d = 0; d < 32; d++) acc[d] += p * Vs[c + j][d];
            }
            m = mx;
        }
        __syncthreads();
    }

    float inv = 1.0f / l;
    float* dst = &att[(size_t)(rbase + t) * W + h * ROPE];
    #pragma unroll
    for (int d = 0; d < 32; d++) dst[d] = acc[d] * inv;
}

// ---------------------------------------------------------------------------
// Launch
// ---------------------------------------------------------------------------
extern "C" void kernel_launch(void* const* d_in, const int* in_sizes, int n_in,
                              void* d_out, int out_size)
{
    const float* x   = (const float*)d_in[0];
    const float* Wq  = (const float*)d_in[1];
    const float* Wkv = (const float*)d_in[2];
    const float* Wk  = (const float*)d_in[3];
    const float* Wv  = (const float*)d_in[4];
    const float* Wo  = (const float*)d_in[5];
    const float* qg  = (const float*)d_in[6];
    const float* kg  = (const float*)d_in[7];
    float* out = (float*)d_out;

    float *pq, *pqr, *pkv, *pk, *pv, *patt, *pwop;
    cudaGetSymbolAddress((void**)&pq,   g_q);
    cudaGetSymbolAddress((void**)&pqr,  g_qr);
    cudaGetSymbolAddress((void**)&pkv,  g_kv);
    cudaGetSymbolAddress((void**)&pk,   g_k);
    cudaGetSymbolAddress((void**)&pv,   g_v);
    cudaGetSymbolAddress((void**)&patt, g_att);
    cudaGetSymbolAddress((void**)&pwop, g_wop);

    pack_wo_kernel<<<(HH * ROPE * DD + 255) / 256, 256>>>(Wo, pwop);

    // q = x @ Wq   (8192,1024,1024)
    gemm_tf32<<<dim3(DD / 128, ROWS / 128), 256>>>(ROWS, DD, DD, x, Wq, pq);
    // kv = x @ Wkv (8192,128,1024)
    gemm_tf32<<<dim3(LAT / 128, ROWS / 128), 256>>>(ROWS, LAT, DD, x, Wkv, pkv);

    {
        int warps = ROWS * HH;
        qnorm_kernel<<<(warps * 32 + 127) / 128, 128>>>(pq, qg, pqr);
    }

    // k = kv @ Wk ; v = kv @ Wv  (8192,512,128)
    gemm_tf32<<<dim3((HH * ROPE) / 128, ROWS / 128), 256>>>(ROWS, HH * ROPE, LAT, pkv, Wk, pk);
    gemm_tf32<<<dim3((HH * ROPE) / 128, ROWS / 128), 256>>>(ROWS, HH * ROPE, LAT, pkv, Wv, pv);

    {
        int warps = ROWS * HH;
        knorm_kernel<<<(warps * 32 + 127) / 128, 128>>>(pk, kg);
    }

    attn_kernel<<<dim3(TT / BQ, BB * HH), 64>>>(pqr, pk, pv, patt);

    // out = att @ WoP  (8192,1024,512)
    gemm_tf32<<<dim3(DD / 128, ROWS / 128), 256>>>(ROWS, DD, HH * ROPE, patt, pwop, out);
}

// round 6
// speedup vs baseline: 2.6464x; 1.8258x over previous
#include <cuda_runtime.h>
#include <cuda_bf16.h>
#include <math.h>

// Problem constants
#define BB   4
#define TT   2048
#define DD   1024
#define HH   16
#define HD   64
#define LAT  128
#define ROPE 32
#define ROWS (BB*TT)          // 8192
#define EPSV 1e-6f

// Scratch
__device__ float g_q  [ROWS * DD];
__device__ float g_qr [ROWS * HH * ROPE];
__device__ float g_kv [ROWS * LAT];
__device__ float g_k  [ROWS * HH * ROPE];
__device__ float g_v  [ROWS * HH * ROPE];
__device__ float g_att[ROWS * HH * ROPE];
__device__ float g_wop[HH * ROPE * DD];

// ---------------------------------------------------------------------------
// fp32 -> tf32 bits, round-to-nearest
// ---------------------------------------------------------------------------
__device__ __forceinline__ unsigned f2tf(float f) {
    unsigned u;
    asm("cvt.rna.tf32.f32 %0, %1;" : "=r"(u) : "f"(f));
    return u;
}

__device__ __forceinline__ void mma_tf32(
    float* c, unsigned a0, unsigned a1, unsigned a2, unsigned a3,
    unsigned b0, unsigned b1)
{
    asm volatile(
        "mma.sync.aligned.m16n8k8.row.col.f32.tf32.tf32.f32 "
        "{%0,%1,%2,%3}, {%4,%5,%6,%7}, {%8,%9}, {%0,%1,%2,%3};"
        : "+f"(c[0]), "+f"(c[1]), "+f"(c[2]), "+f"(c[3])
        : "r"(a0), "r"(a1), "r"(a2), "r"(a3), "r"(b0), "r"(b1));
}

// ---------------------------------------------------------------------------
// TF32 tensor-core GEMM: C[M,N] = A[M,K] @ B[K,N], row-major.
// BM=BN=128, BK=16, 256 threads = 8 warps (2x4); warp = 64x32 via m16n8k8.
// ---------------------------------------------------------------------------
__global__ __launch_bounds__(256) void gemm_tf32(
    int M, int N, int K,
    const float* __restrict__ A, const float* __restrict__ B,
    float* __restrict__ C)
{
    __shared__ unsigned As[128][20];
    __shared__ unsigned Bs[16][136];

    const int tid  = threadIdx.x;
    const int lane = tid & 31;
    const int warp = tid >> 5;
    const int g    = lane >> 2;
    const int t4   = lane & 3;
    const int wr   = warp >> 2;
    const int wc   = warp & 3;

    const int bM = blockIdx.y * 128;
    const int bN = blockIdx.x * 128;

    const int aRow = tid >> 2;
    const int aCol = (tid & 3) * 4;
    const int bRow = tid >> 5;
    const int bCol = (tid & 31) * 4;

    float acc[4][4][4];
    #pragma unroll
    for (int i = 0; i < 4; i++)
        #pragma unroll
        for (int j = 0; j < 4; j++)
            #pragma unroll
            for (int c = 0; c < 4; c++) acc[i][j][c] = 0.f;

    for (int k0 = 0; k0 < K; k0 += 16) {
        #pragma unroll
        for (int p = 0; p < 2; p++) {
            int r = aRow + p * 64;
            float4 v = *(const float4*)&A[(size_t)(bM + r) * K + k0 + aCol];
            As[r][aCol + 0] = f2tf(v.x);
            As[r][aCol + 1] = f2tf(v.y);
            As[r][aCol + 2] = f2tf(v.z);
            As[r][aCol + 3] = f2tf(v.w);
        }
        #pragma unroll
        for (int p = 0; p < 2; p++) {
            int r = bRow + p * 8;
            float4 v = *(const float4*)&B[(size_t)(k0 + r) * N + bN + bCol];
            uint4 u;
            u.x = f2tf(v.x); u.y = f2tf(v.y); u.z = f2tf(v.z); u.w = f2tf(v.w);
            *(uint4*)&Bs[r][bCol] = u;
        }
        __syncthreads();

        #pragma unroll
        for (int kk = 0; kk < 16; kk += 8) {
            unsigned a[4][4], b[4][2];
            #pragma unroll
            for (int mi = 0; mi < 4; mi++) {
                int row = wr * 64 + mi * 16 + g;
                a[mi][0] = As[row    ][kk + t4];
                a[mi][1] = As[row + 8][kk + t4];
                a[mi][2] = As[row    ][kk + t4 + 4];
                a[mi][3] = As[row + 8][kk + t4 + 4];
            }
            #pragma unroll
            for (int ni = 0; ni < 4; ni++) {
                int col = wc * 32 + ni * 8 + g;
                b[ni][0] = Bs[kk + t4    ][col];
                b[ni][1] = Bs[kk + t4 + 4][col];
            }
            #pragma unroll
            for (int mi = 0; mi < 4; mi++)
                #pragma unroll
                for (int ni = 0; ni < 4; ni++)
                    mma_tf32(acc[mi][ni], a[mi][0], a[mi][1], a[mi][2], a[mi][3],
                             b[ni][0], b[ni][1]);
        }
        __syncthreads();
    }

    #pragma unroll
    for (int mi = 0; mi < 4; mi++) {
        #pragma unroll
        for (int ni = 0; ni < 4; ni++) {
            int row = bM + wr * 64 + mi * 16 + g;
            int col = bN + wc * 32 + ni * 8 + 2 * t4;
            *(float2*)&C[(size_t)row * N + col] =
                make_float2(acc[mi][ni][0], acc[mi][ni][1]);
            *(float2*)&C[(size_t)(row + 8) * N + col] =
                make_float2(acc[mi][ni][2], acc[mi][ni][3]);
        }
    }
}

// ---------------------------------------------------------------------------
// Pack Wo
// ---------------------------------------------------------------------------
__global__ void pack_wo_kernel(const float* __restrict__ Wo, float* __restrict__ WoP)
{
    int idx = blockIdx.x * blockDim.x + threadIdx.x;
    if (idx >= HH * ROPE * DD) return;
    int r = idx >> 10;
    int n = idx & 1023;
    int h = r >> 5;
    int d = r & 31;
    WoP[idx] = Wo[(size_t)(h * HD + d) * DD + n];
}

// ---------------------------------------------------------------------------
// Q RMSNorm (rms over 64 dims, keep first 32)
// ---------------------------------------------------------------------------
__global__ void qnorm_kernel(const float* __restrict__ q,
                             const float* __restrict__ qg,
                             float* __restrict__ qr)
{
    int warp = (blockIdx.x * blockDim.x + threadIdx.x) >> 5;
    int lane = threadIdx.x & 31;
    if (warp >= ROWS * HH) return;
    int row = warp >> 4;
    int h   = warp & 15;
    const float* base = q + (size_t)row * DD + h * HD;
    float v0 = base[lane];
    float v1 = base[lane + 32];
    float ss = v0 * v0 + v1 * v1;
    #pragma unroll
    for (int o = 16; o > 0; o >>= 1) ss += __shfl_xor_sync(0xffffffffu, ss, o);
    float rinv = rsqrtf(ss * (1.0f / HD) + EPSV);
    qr[(size_t)row * (HH * ROPE) + h * ROPE + lane] = qg[lane] * v0 * rinv;
}

// ---------------------------------------------------------------------------
// K RMSNorm (32 dims, in place)
// ---------------------------------------------------------------------------
__global__ void knorm_kernel(float* __restrict__ k, const float* __restrict__ kg)
{
    int warp = (blockIdx.x * blockDim.x + threadIdx.x) >> 5;
    int lane = threadIdx.x & 31;
    if (warp >= ROWS * HH) return;
    float* base = k + (size_t)warp * ROPE;
    float v = base[lane];
    float ss = v * v;
    #pragma unroll
    for (int o = 16; o > 0; o >>= 1) ss += __shfl_xor_sync(0xffffffffu, ss, o);
    float rinv = rsqrtf(ss * (1.0f / ROPE) + EPSV);
    base[lane] = kg[lane] * v * rinv;
}

// ---------------------------------------------------------------------------
// Tensor-core flash attention (causal). One CTA = one (b,h) x 64-query tile.
// 4 warps / 128 threads; warp w owns query rows [16w, 16w+16).
// S = Q@K^T via m16n8k8 tf32 (k=32); P@V via m16n8k8 (k=64).
// P round-trips through the warp's private smem stripe (syncwarp only).
// QPs is 68 wide: Q uses cols 0..31, P tiles use cols 0..63 (was the R5 OOB).
// ---------------------------------------------------------------------------
__global__ __launch_bounds__(128) void attn_mma_kernel(
    const float* __restrict__ qr, const float* __restrict__ kk_,
    const float* __restrict__ vv, float* __restrict__ att)
{
    // Bank analysis:
    //  Ks stride 36:  S b-frag bank = 4g+t4+8ks      -> conflict-free
    //  Vs stride 40:  PV b-frag bank = 8(t4+ni)+g    -> conflict-free
    //  QPs stride 68: Q/P a-frag bank = 4g+t4+8ks    -> conflict-free
    __shared__ unsigned Ks [64][36];
    __shared__ unsigned Vs [64][40];
    __shared__ unsigned QPs[64][68];

    const int qt  = blockIdx.x;
    const int bh  = blockIdx.y;
    const int b   = bh >> 4;
    const int h   = bh & 15;
    const int tid = threadIdx.x;
    const int lane = tid & 31;
    const int w    = tid >> 5;
    const int g    = lane >> 2;
    const int t4   = lane & 3;
    const int rbase = b * TT;
    const int W = HH * ROPE;   // 512

    // stage Q tile (fp32 bits)
    for (int f = tid; f < 64 * 8; f += 128) {
        int row = f >> 3, c4 = (f & 7) * 4;
        float4 v = *(const float4*)&qr[(size_t)(rbase + qt * 64 + row) * W + h * ROPE + c4];
        QPs[row][c4 + 0] = __float_as_uint(v.x);
        QPs[row][c4 + 1] = __float_as_uint(v.y);
        QPs[row][c4 + 2] = __float_as_uint(v.z);
        QPs[row][c4 + 3] = __float_as_uint(v.w);
    }
    __syncthreads();

    // build Q fragments (fold in 1/sqrt(HD) = 0.125)
    const int prow = w * 16 + g;
    unsigned aq[4][4];
    #pragma unroll
    for (int ks = 0; ks < 4; ks++) {
        aq[ks][0] = f2tf(0.125f * __uint_as_float(QPs[prow    ][ks * 8 + t4]));
        aq[ks][1] = f2tf(0.125f * __uint_as_float(QPs[prow + 8][ks * 8 + t4]));
        aq[ks][2] = f2tf(0.125f * __uint_as_float(QPs[prow    ][ks * 8 + t4 + 4]));
        aq[ks][3] = f2tf(0.125f * __uint_as_float(QPs[prow + 8][ks * 8 + t4 + 4]));
    }
    // P writes below touch only warp w's own stripe (rows 16w..16w+15),
    // the same rows this warp just read -> no cross-warp hazard on QPs.

    float m0 = -INFINITY, m1 = -INFINITY, l0 = 0.f, l1 = 0.f;
    float o[4][4];
    #pragma unroll
    for (int ni = 0; ni < 4; ni++)
        #pragma unroll
        for (int c = 0; c < 4; c++) o[ni][c] = 0.f;

    for (int kt = 0; kt <= qt; kt++) {
        __syncthreads();   // previous iteration's Ks/Vs reads complete
        for (int f = tid; f < 64 * 8; f += 128) {
            int row = f >> 3, c4 = (f & 7) * 4;
            size_t gaddr = (size_t)(rbase + kt * 64 + row) * W + h * ROPE + c4;
            float4 kv4 = *(const float4*)&kk_[gaddr];
            Ks[row][c4 + 0] = f2tf(kv4.x);
            Ks[row][c4 + 1] = f2tf(kv4.y);
            Ks[row][c4 + 2] = f2tf(kv4.z);
            Ks[row][c4 + 3] = f2tf(kv4.w);
            float4 vv4 = *(const float4*)&vv[gaddr];
            Vs[row][c4 + 0] = f2tf(vv4.x);
            Vs[row][c4 + 1] = f2tf(vv4.y);
            Vs[row][c4 + 2] = f2tf(vv4.z);
            Vs[row][c4 + 3] = f2tf(vv4.w);
        }
        __syncthreads();

        // S = Q @ K^T : 8 n-tiles x 4 k-steps
        float s[8][4];
        #pragma unroll
        for (int j = 0; j < 8; j++)
            #pragma unroll
            for (int c = 0; c < 4; c++) s[j][c] = 0.f;

        #pragma unroll
        for (int ks = 0; ks < 4; ks++) {
            #pragma unroll
            for (int j = 0; j < 8; j++) {
                unsigned b0 = Ks[8 * j + g][ks * 8 + t4];
                unsigned b1 = Ks[8 * j + g][ks * 8 + t4 + 4];
                mma_tf32(s[j], aq[ks][0], aq[ks][1], aq[ks][2], aq[ks][3], b0, b1);
            }
        }

        // causal mask on diagonal tile
        if (kt == qt) {
            #pragma unroll
            for (int j = 0; j < 8; j++) {
                int cl = 8 * j + 2 * t4;
                if (cl     > prow    ) s[j][0] = -INFINITY;
                if (cl + 1 > prow    ) s[j][1] = -INFINITY;
                if (cl     > prow + 8) s[j][2] = -INFINITY;
                if (cl + 1 > prow + 8) s[j][3] = -INFINITY;
            }
        }

        // online softmax (rows prow, prow+8); reduce over 4-lane t4 group
        float mx0 = m0, mx1 = m1;
        #pragma unroll
        for (int j = 0; j < 8; j++) {
            mx0 = fmaxf(mx0, fmaxf(s[j][0], s[j][1]));
            mx1 = fmaxf(mx1, fmaxf(s[j][2], s[j][3]));
        }
        mx0 = fmaxf(mx0, __shfl_xor_sync(0xffffffffu, mx0, 1));
        mx0 = fmaxf(mx0, __shfl_xor_sync(0xffffffffu, mx0, 2));
        mx1 = fmaxf(mx1, __shfl_xor_sync(0xffffffffu, mx1, 1));
        mx1 = fmaxf(mx1, __shfl_xor_sync(0xffffffffu, mx1, 2));

        float sc0 = __expf(m0 - mx0);
        float sc1 = __expf(m1 - mx1);
        m0 = mx0; m1 = mx1;

        float ls0 = 0.f, ls1 = 0.f;
        #pragma unroll
        for (int j = 0; j < 8; j++) {
            float p0 = __expf(s[j][0] - m0);
            float p1 = __expf(s[j][1] - m0);
            float p2 = __expf(s[j][2] - m1);
            float p3 = __expf(s[j][3] - m1);
            ls0 += p0 + p1;
            ls1 += p2 + p3;
            QPs[prow    ][8 * j + 2 * t4    ] = f2tf(p0);
            QPs[prow    ][8 * j + 2 * t4 + 1] = f2tf(p1);
            QPs[prow + 8][8 * j + 2 * t4    ] = f2tf(p2);
            QPs[prow + 8][8 * j + 2 * t4 + 1] = f2tf(p3);
        }
        ls0 += __shfl_xor_sync(0xffffffffu, ls0, 1);
        ls0 += __shfl_xor_sync(0xffffffffu, ls0, 2);
        ls1 += __shfl_xor_sync(0xffffffffu, ls1, 1);
        ls1 += __shfl_xor_sync(0xffffffffu, ls1, 2);
        l0 = l0 * sc0 + ls0;
        l1 = l1 * sc1 + ls1;

        #pragma unroll
        for (int ni = 0; ni < 4; ni++) {
            o[ni][0] *= sc0; o[ni][1] *= sc0;
            o[ni][2] *= sc1; o[ni][3] *= sc1;
        }
        __syncwarp();   // P stripe visible to all lanes of this warp

        // O += P @ V : 4 n-tiles x 8 k-steps (k = 64 keys)
        #pragma unroll
        for (int ks = 0; ks < 8; ks++) {
            unsigned a0 = QPs[prow    ][ks * 8 + t4];
            unsigned a1 = QPs[prow + 8][ks * 8 + t4];
            unsigned a2 = QPs[prow    ][ks * 8 + t4 + 4];
            unsigned a3 = QPs[prow + 8][ks * 8 + t4 + 4];
            #pragma unroll
            for (int ni = 0; ni < 4; ni++) {
                unsigned b0 = Vs[ks * 8 + t4    ][8 * ni + g];
                unsigned b1 = Vs[ks * 8 + t4 + 4][8 * ni + g];
                mma_tf32(o[ni], a0, a1, a2, a3, b0, b1);
            }
        }
        __syncwarp();   // P reads done before next iteration overwrites stripe
    }

    // epilogue
    float inv0 = 1.0f / l0;
    float inv1 = 1.0f / l1;
    int grow = rbase + qt * 64 + prow;
    float* dst0 = &att[(size_t)grow * W + h * ROPE];
    float* dst1 = dst0 + (size_t)8 * W;
    #pragma unroll
    for (int ni = 0; ni < 4; ni++) {
        int col = 8 * ni + 2 * t4;
        *(float2*)&dst0[col] = make_float2(o[ni][0] * inv0, o[ni][1] * inv0);
        *(float2*)&dst1[col] = make_float2(o[ni][2] * inv1, o[ni][3] * inv1);
    }
}

// ---------------------------------------------------------------------------
// Launch
// ---------------------------------------------------------------------------
extern "C" void kernel_launch(void* const* d_in, const int* in_sizes, int n_in,
                              void* d_out, int out_size)
{
    const float* x   = (const float*)d_in[0];
    const float* Wq  = (const float*)d_in[1];
    const float* Wkv = (const float*)d_in[2];
    const float* Wk  = (const float*)d_in[3];
    const float* Wv  = (const float*)d_in[4];
    const float* Wo  = (const float*)d_in[5];
    const float* qg  = (const float*)d_in[6];
    const float* kg  = (const float*)d_in[7];
    float* out = (float*)d_out;

    float *pq, *pqr, *pkv, *pk, *pv, *patt, *pwop;
    cudaGetSymbolAddress((void**)&pq,   g_q);
    cudaGetSymbolAddress((void**)&pqr,  g_qr);
    cudaGetSymbolAddress((void**)&pkv,  g_kv);
    cudaGetSymbolAddress((void**)&pk,   g_k);
    cudaGetSymbolAddress((void**)&pv,   g_v);
    cudaGetSymbolAddress((void**)&patt, g_att);
    cudaGetSymbolAddress((void**)&pwop, g_wop);

    pack_wo_kernel<<<(HH * ROPE * DD + 255) / 256, 256>>>(Wo, pwop);

    // q = x @ Wq   (8192,1024,1024)
    gemm_tf32<<<dim3(DD / 128, ROWS / 128), 256>>>(ROWS, DD, DD, x, Wq, pq);
    // kv = x @ Wkv (8192,128,1024)
    gemm_tf32<<<dim3(LAT / 128, ROWS / 128), 256>>>(ROWS, LAT, DD, x, Wkv, pkv);

    {
        int warps = ROWS * HH;
        qnorm_kernel<<<(warps * 32 + 127) / 128, 128>>>(pq, qg, pqr);
    }

    // k = kv @ Wk ; v = kv @ Wv  (8192,512,128)
    gemm_tf32<<<dim3((HH * ROPE) / 128, ROWS / 128), 256>>>(ROWS, HH * ROPE, LAT, pkv, Wk, pk);
    gemm_tf32<<<dim3((HH * ROPE) / 128, ROWS / 128), 256>>>(ROWS, HH * ROPE, LAT, pkv, Wv, pv);

    {
        int warps = ROWS * HH;
        knorm_kernel<<<(warps * 32 + 127) / 128, 128>>>(pk, kg);
    }

    // tensor-core flash attention
    attn_mma_kernel<<<dim3(TT / 64, BB * HH), 128>>>(pqr, pk, pv, patt);

    // out = att @ WoP  (8192,1024,512)
    gemm_tf32<<<dim3(DD / 128, ROWS / 128), 256>>>(ROWS, DD, HH * ROPE, patt, pwop, out);
}

// round 7
// speedup vs baseline: 2.9775x; 1.1251x over previous
#include <cuda_runtime.h>
#include <cuda_bf16.h>
#include <math.h>

// Problem constants
#define BB   4
#define TT   2048
#define DD   1024
#define HH   16
#define HD   64
#define LAT  128
#define ROPE 32
#define ROWS (BB*TT)          // 8192
#define EPSV 1e-6f

// Scratch
__device__ float g_qr [ROWS * HH * ROPE]; // normalized q (first 32 dims/head)
__device__ float g_kv [ROWS * LAT];
__device__ float g_k  [ROWS * HH * ROPE]; // normalized k
__device__ float g_v  [ROWS * HH * ROPE];
__device__ float g_att[ROWS * HH * ROPE];
__device__ float g_wop[HH * ROPE * DD];

// ---------------------------------------------------------------------------
// fp32 -> tf32 bits, round-to-nearest
// ---------------------------------------------------------------------------
__device__ __forceinline__ unsigned f2tf(float f) {
    unsigned u;
    asm("cvt.rna.tf32.f32 %0, %1;" : "=r"(u) : "f"(f));
    return u;
}

__device__ __forceinline__ void mma_tf32(
    float* c, unsigned a0, unsigned a1, unsigned a2, unsigned a3,
    unsigned b0, unsigned b1)
{
    asm volatile(
        "mma.sync.aligned.m16n8k8.row.col.f32.tf32.tf32.f32 "
        "{%0,%1,%2,%3}, {%4,%5,%6,%7}, {%8,%9}, {%0,%1,%2,%3};"
        : "+f"(c[0]), "+f"(c[1]), "+f"(c[2]), "+f"(c[3])
        : "r"(a0), "r"(a1), "r"(a2), "r"(a3), "r"(b0), "r"(b1));
}

// ---------------------------------------------------------------------------
// TF32 tensor-core GEMM, double-buffered smem pipeline.
// C[M,N] = A[M,K] @ B[K,N], row-major. BM=BN=128, BK=16, 256 thr = 8 warps.
// MODE 0: plain store to C (ldC = N)
// MODE 1: fused K-RMSNorm over each 32-col head (warp-local), gvec = k_g
// MODE 2: fused Q-RMSNorm over each 64-col head (warp-pair via smem),
//         writes only the first 32 dims/head to C with ldC = 512, gvec = q_g
// ---------------------------------------------------------------------------
template<int MODE>
__global__ __launch_bounds__(256) void gemm_tf32(
    int M, int N, int K,
    const float* __restrict__ A, const float* __restrict__ B,
    float* __restrict__ C, const float* __restrict__ gvec)
{
    __shared__ unsigned As[2][128][20];
    __shared__ unsigned Bs[2][16][136];
    __shared__ float ssbuf[128][4];      // MODE 2 partial sums (2 KB)

    const int tid  = threadIdx.x;
    const int lane = tid & 31;
    const int warp = tid >> 5;
    const int g    = lane >> 2;
    const int t4   = lane & 3;
    const int wr   = warp >> 2;
    const int wc   = warp & 3;

    const int bM = blockIdx.y * 128;
    const int bN = blockIdx.x * 128;

    const int aRow = tid >> 2;
    const int aCol = (tid & 3) * 4;
    const int bRow = tid >> 5;
    const int bCol = (tid & 31) * 4;

    float acc[4][4][4];
    #pragma unroll
    for (int i = 0; i < 4; i++)
        #pragma unroll
        for (int j = 0; j < 4; j++)
            #pragma unroll
            for (int c = 0; c < 4; c++) acc[i][j][c] = 0.f;

    const float* Ab = A + (size_t)bM * K;
    const float* Bb = B + bN;

    float4 ra0, ra1, rb0, rb1;

    // prologue: tile 0 -> regs -> smem buf 0
    ra0 = *(const float4*)&Ab[(size_t)aRow * K + aCol];
    ra1 = *(const float4*)&Ab[(size_t)(aRow + 64) * K + aCol];
    rb0 = *(const float4*)&Bb[(size_t)bRow * N + bCol];
    rb1 = *(const float4*)&Bb[(size_t)(bRow + 8) * N + bCol];
    {
        As[0][aRow][aCol+0] = f2tf(ra0.x); As[0][aRow][aCol+1] = f2tf(ra0.y);
        As[0][aRow][aCol+2] = f2tf(ra0.z); As[0][aRow][aCol+3] = f2tf(ra0.w);
        As[0][aRow+64][aCol+0] = f2tf(ra1.x); As[0][aRow+64][aCol+1] = f2tf(ra1.y);
        As[0][aRow+64][aCol+2] = f2tf(ra1.z); As[0][aRow+64][aCol+3] = f2tf(ra1.w);
        uint4 u0 = make_uint4(f2tf(rb0.x), f2tf(rb0.y), f2tf(rb0.z), f2tf(rb0.w));
        uint4 u1 = make_uint4(f2tf(rb1.x), f2tf(rb1.y), f2tf(rb1.z), f2tf(rb1.w));
        *(uint4*)&Bs[0][bRow][bCol]     = u0;
        *(uint4*)&Bs[0][bRow + 8][bCol] = u1;
    }
    __syncthreads();

    const int nIter = K >> 4;
    for (int it = 0; it < nIter; it++) {
        const int p = it & 1;
        // prefetch next tile (global -> regs), latency hidden by compute
        if (it + 1 < nIter) {
            int k0 = (it + 1) << 4;
            ra0 = *(const float4*)&Ab[(size_t)aRow * K + k0 + aCol];
            ra1 = *(const float4*)&Ab[(size_t)(aRow + 64) * K + k0 + aCol];
            rb0 = *(const float4*)&Bb[(size_t)(k0 + bRow) * N + bCol];
            rb1 = *(const float4*)&Bb[(size_t)(k0 + bRow + 8) * N + bCol];
        }

        #pragma unroll
        for (int kk = 0; kk < 16; kk += 8) {
            unsigned a[4][4], b[4][2];
            #pragma unroll
            for (int mi = 0; mi < 4; mi++) {
                int row = wr * 64 + mi * 16 + g;
                a[mi][0] = As[p][row    ][kk + t4];
                a[mi][1] = As[p][row + 8][kk + t4];
                a[mi][2] = As[p][row    ][kk + t4 + 4];
                a[mi][3] = As[p][row + 8][kk + t4 + 4];
            }
            #pragma unroll
            for (int ni = 0; ni < 4; ni++) {
                int col = wc * 32 + ni * 8 + g;
                b[ni][0] = Bs[p][kk + t4    ][col];
                b[ni][1] = Bs[p][kk + t4 + 4][col];
            }
            #pragma unroll
            for (int mi = 0; mi < 4; mi++)
                #pragma unroll
                for (int ni = 0; ni < 4; ni++)
                    mma_tf32(acc[mi][ni], a[mi][0], a[mi][1], a[mi][2], a[mi][3],
                             b[ni][0], b[ni][1]);
        }

        // stage next tile into the other buffer (prev reads of it were fenced
        // by the syncthreads at the end of the previous iteration)
        if (it + 1 < nIter) {
            const int q = p ^ 1;
            As[q][aRow][aCol+0] = f2tf(ra0.x); As[q][aRow][aCol+1] = f2tf(ra0.y);
            As[q][aRow][aCol+2] = f2tf(ra0.z); As[q][aRow][aCol+3] = f2tf(ra0.w);
            As[q][aRow+64][aCol+0] = f2tf(ra1.x); As[q][aRow+64][aCol+1] = f2tf(ra1.y);
            As[q][aRow+64][aCol+2] = f2tf(ra1.z); As[q][aRow+64][aCol+3] = f2tf(ra1.w);
            uint4 u0 = make_uint4(f2tf(rb0.x), f2tf(rb0.y), f2tf(rb0.z), f2tf(rb0.w));
            uint4 u1 = make_uint4(f2tf(rb1.x), f2tf(rb1.y), f2tf(rb1.z), f2tf(rb1.w));
            *(uint4*)&Bs[q][bRow][bCol]     = u0;
            *(uint4*)&Bs[q][bRow + 8][bCol] = u1;
        }
        __syncthreads();
    }

    // ---------------- epilogue ----------------
    if (MODE == 0) {
        #pragma unroll
        for (int mi = 0; mi < 4; mi++) {
            #pragma unroll
            for (int ni = 0; ni < 4; ni++) {
                int row = bM + wr * 64 + mi * 16 + g;
                int col = bN + wc * 32 + ni * 8 + 2 * t4;
                *(float2*)&C[(size_t)row * N + col] =
                    make_float2(acc[mi][ni][0], acc[mi][ni][1]);
                *(float2*)&C[(size_t)(row + 8) * N + col] =
                    make_float2(acc[mi][ni][2], acc[mi][ni][3]);
            }
        }
    } else if (MODE == 1) {
        // warp's 32 cols == one K head: register + shuffle reduction
        #pragma unroll
        for (int mi = 0; mi < 4; mi++) {
            float ss0 = 0.f, ss1 = 0.f;
            #pragma unroll
            for (int ni = 0; ni < 4; ni++) {
                ss0 += acc[mi][ni][0]*acc[mi][ni][0] + acc[mi][ni][1]*acc[mi][ni][1];
                ss1 += acc[mi][ni][2]*acc[mi][ni][2] + acc[mi][ni][3]*acc[mi][ni][3];
            }
            ss0 += __shfl_xor_sync(0xffffffffu, ss0, 1);
            ss0 += __shfl_xor_sync(0xffffffffu, ss0, 2);
            ss1 += __shfl_xor_sync(0xffffffffu, ss1, 1);
            ss1 += __shfl_xor_sync(0xffffffffu, ss1, 2);
            float rinv0 = rsqrtf(ss0 * (1.0f / ROPE) + EPSV);
            float rinv1 = rsqrtf(ss1 * (1.0f / ROPE) + EPSV);
            int row = bM + wr * 64 + mi * 16 + g;
            #pragma unroll
            for (int ni = 0; ni < 4; ni++) {
                int d   = ni * 8 + 2 * t4;            // col within head
                int col = bN + wc * 32 + d;
                float g0 = gvec[d], g1 = gvec[d + 1];
                *(float2*)&C[(size_t)row * N + col] =
                    make_float2(acc[mi][ni][0] * rinv0 * g0,
                                acc[mi][ni][1] * rinv0 * g1);
                *(float2*)&C[(size_t)(row + 8) * N + col] =
                    make_float2(acc[mi][ni][2] * rinv1 * g0,
                                acc[mi][ni][3] * rinv1 * g1);
            }
        }
    } else {
        // MODE 2: Q head = 64 cols = warp pair (wc, wc^1); smem partial sums
        #pragma unroll
        for (int mi = 0; mi < 4; mi++) {
            float ss0 = 0.f, ss1 = 0.f;
            #pragma unroll
            for (int ni = 0; ni < 4; ni++) {
                ss0 += acc[mi][ni][0]*acc[mi][ni][0] + acc[mi][ni][1]*acc[mi][ni][1];
                ss1 += acc[mi][ni][2]*acc[mi][ni][2] + acc[mi][ni][3]*acc[mi][ni][3];
            }
            ss0 += __shfl_xor_sync(0xffffffffu, ss0, 1);
            ss0 += __shfl_xor_sync(0xffffffffu, ss0, 2);
            ss1 += __shfl_xor_sync(0xffffffffu, ss1, 1);
            ss1 += __shfl_xor_sync(0xffffffffu, ss1, 2);
            if (t4 == 0) {
                int lr = wr * 64 + mi * 16 + g;
                ssbuf[lr][wc]     = ss0;
                ssbuf[lr + 8][wc] = ss1;
            }
        }
        __syncthreads();
        if ((wc & 1) == 0) {
            #pragma unroll
            for (int mi = 0; mi < 4; mi++) {
                int lr = wr * 64 + mi * 16 + g;
                float t0 = ssbuf[lr][wc] + ssbuf[lr][wc ^ 1];
                float t1 = ssbuf[lr + 8][wc] + ssbuf[lr + 8][wc ^ 1];
                float rinv0 = rsqrtf(t0 * (1.0f / HD) + EPSV);
                float rinv1 = rsqrtf(t1 * (1.0f / HD) + EPSV);
                int row = bM + lr;
                #pragma unroll
                for (int ni = 0; ni < 4; ni++) {
                    int d  = ni * 8 + 2 * t4;              // 0..31 (wc even)
                    int cg = bN + wc * 32 + d;             // global q col
                    int qc = (cg >> 6) * 32 + d;           // packed qr col
                    float g0 = gvec[d], g1 = gvec[d + 1];
                    *(float2*)&C[(size_t)row * 512 + qc] =
                        make_float2(acc[mi][ni][0] * rinv0 * g0,
                                    acc[mi][ni][1] * rinv0 * g1);
                    *(float2*)&C[(size_t)(row + 8) * 512 + qc] =
                        make_float2(acc[mi][ni][2] * rinv1 * g0,
                                    acc[mi][ni][3] * rinv1 * g1);
                }
            }
        }
    }
}

// ---------------------------------------------------------------------------
// Pack Wo
// ---------------------------------------------------------------------------
__global__ void pack_wo_kernel(const float* __restrict__ Wo, float* __restrict__ WoP)
{
    int idx = blockIdx.x * blockDim.x + threadIdx.x;
    if (idx >= HH * ROPE * DD) return;
    int r = idx >> 10;
    int n = idx & 1023;
    int h = r >> 5;
    int d = r & 31;
    WoP[idx] = Wo[(size_t)(h * HD + d) * DD + n];
}

// ---------------------------------------------------------------------------
// Tensor-core flash attention (causal) — unchanged from R6 (verified).
// ---------------------------------------------------------------------------
__global__ __launch_bounds__(128) void attn_mma_kernel(
    const float* __restrict__ qr, const float* __restrict__ kk_,
    const float* __restrict__ vv, float* __restrict__ att)
{
    __shared__ unsigned Ks [64][36];
    __shared__ unsigned Vs [64][40];
    __shared__ unsigned QPs[64][68];

    const int qt  = blockIdx.x;
    const int bh  = blockIdx.y;
    const int b   = bh >> 4;
    const int h   = bh & 15;
    const int tid = threadIdx.x;
    const int lane = tid & 31;
    const int w    = tid >> 5;
    const int g    = lane >> 2;
    const int t4   = lane & 3;
    const int rbase = b * TT;
    const int W = HH * ROPE;

    for (int f = tid; f < 64 * 8; f += 128) {
        int row = f >> 3, c4 = (f & 7) * 4;
        float4 v = *(const float4*)&qr[(size_t)(rbase + qt * 64 + row) * W + h * ROPE + c4];
        QPs[row][c4 + 0] = __float_as_uint(v.x);
        QPs[row][c4 + 1] = __float_as_uint(v.y);
        QPs[row][c4 + 2] = __float_as_uint(v.z);
        QPs[row][c4 + 3] = __float_as_uint(v.w);
    }
    __syncthreads();

    const int prow = w * 16 + g;
    unsigned aq[4][4];
    #pragma unroll
    for (int ks = 0; ks < 4; ks++) {
        aq[ks][0] = f2tf(0.125f * __uint_as_float(QPs[prow    ][ks * 8 + t4]));
        aq[ks][1] = f2tf(0.125f * __uint_as_float(QPs[prow + 8][ks * 8 + t4]));
        aq[ks][2] = f2tf(0.125f * __uint_as_float(QPs[prow    ][ks * 8 + t4 + 4]));
        aq[ks][3] = f2tf(0.125f * __uint_as_float(QPs[prow + 8][ks * 8 + t4 + 4]));
    }

    float m0 = -INFINITY, m1 = -INFINITY, l0 = 0.f, l1 = 0.f;
    float o[4][4];
    #pragma unroll
    for (int ni = 0; ni < 4; ni++)
        #pragma unroll
        for (int c = 0; c < 4; c++) o[ni][c] = 0.f;

    for (int kt = 0; kt <= qt; kt++) {
        __syncthreads();
        for (int f = tid; f < 64 * 8; f += 128) {
            int row = f >> 3, c4 = (f & 7) * 4;
            size_t gaddr = (size_t)(rbase + kt * 64 + row) * W + h * ROPE + c4;
            float4 kv4 = *(const float4*)&kk_[gaddr];
            Ks[row][c4 + 0] = f2tf(kv4.x);
            Ks[row][c4 + 1] = f2tf(kv4.y);
            Ks[row][c4 + 2] = f2tf(kv4.z);
            Ks[row][c4 + 3] = f2tf(kv4.w);
            float4 vv4 = *(const float4*)&vv[gaddr];
            Vs[row][c4 + 0] = f2tf(vv4.x);
            Vs[row][c4 + 1] = f2tf(vv4.y);
            Vs[row][c4 + 2] = f2tf(vv4.z);
            Vs[row][c4 + 3] = f2tf(vv4.w);
        }
        __syncthreads();

        float s[8][4];
        #pragma unroll
        for (int j = 0; j < 8; j++)
            #pragma unroll
            for (int c = 0; c < 4; c++) s[j][c] = 0.f;

        #pragma unroll
        for (int ks = 0; ks < 4; ks++) {
            #pragma unroll
            for (int j = 0; j < 8; j++) {
                unsigned b0 = Ks[8 * j + g][ks * 8 + t4];
                unsigned b1 = Ks[8 * j + g][ks * 8 + t4 + 4];
                mma_tf32(s[j], aq[ks][0], aq[ks][1], aq[ks][2], aq[ks][3], b0, b1);
            }
        }

        if (kt == qt) {
            #pragma unroll
            for (int j = 0; j < 8; j++) {
                int cl = 8 * j + 2 * t4;
                if (cl     > prow    ) s[j][0] = -INFINITY;
                if (cl + 1 > prow    ) s[j][1] = -INFINITY;
                if (cl     > prow + 8) s[j][2] = -INFINITY;
                if (cl + 1 > prow + 8) s[j][3] = -INFINITY;
            }
        }

        float mx0 = m0, mx1 = m1;
        #pragma unroll
        for (int j = 0; j < 8; j++) {
            mx0 = fmaxf(mx0, fmaxf(s[j][0], s[j][1]));
            mx1 = fmaxf(mx1, fmaxf(s[j][2], s[j][3]));
        }
        mx0 = fmaxf(mx0, __shfl_xor_sync(0xffffffffu, mx0, 1));
        mx0 = fmaxf(mx0, __shfl_xor_sync(0xffffffffu, mx0, 2));
        mx1 = fmaxf(mx1, __shfl_xor_sync(0xffffffffu, mx1, 1));
        mx1 = fmaxf(mx1, __shfl_xor_sync(0xffffffffu, mx1, 2));

        float sc0 = __expf(m0 - mx0);
        float sc1 = __expf(m1 - mx1);
        m0 = mx0; m1 = mx1;

        float ls0 = 0.f, ls1 = 0.f;
        #pragma unroll
        for (int j = 0; j < 8; j++) {
            float p0 = __expf(s[j][0] - m0);
            float p1 = __expf(s[j][1] - m0);
            float p2 = __expf(s[j][2] - m1);
            float p3 = __expf(s[j][3] - m1);
            ls0 += p0 + p1;
            ls1 += p2 + p3;
            QPs[prow    ][8 * j + 2 * t4    ] = f2tf(p0);
            QPs[prow    ][8 * j + 2 * t4 + 1] = f2tf(p1);
            QPs[prow + 8][8 * j + 2 * t4    ] = f2tf(p2);
            QPs[prow + 8][8 * j + 2 * t4 + 1] = f2tf(p3);
        }
        ls0 += __shfl_xor_sync(0xffffffffu, ls0, 1);
        ls0 += __shfl_xor_sync(0xffffffffu, ls0, 2);
        ls1 += __shfl_xor_sync(0xffffffffu, ls1, 1);
        ls1 += __shfl_xor_sync(0xffffffffu, ls1, 2);
        l0 = l0 * sc0 + ls0;
        l1 = l1 * sc1 + ls1;

        #pragma unroll
        for (int ni = 0; ni < 4; ni++) {
            o[ni][0] *= sc0; o[ni][1] *= sc0;
            o[ni][2] *= sc1; o[ni][3] *= sc1;
        }
        __syncwarp();

        #pragma unroll
        for (int ks = 0; ks < 8; ks++) {
            unsigned a0 = QPs[prow    ][ks * 8 + t4];
            unsigned a1 = QPs[prow + 8][ks * 8 + t4];
            unsigned a2 = QPs[prow    ][ks * 8 + t4 + 4];
            unsigned a3 = QPs[prow + 8][ks * 8 + t4 + 4];
            #pragma unroll
            for (int ni = 0; ni < 4; ni++) {
                unsigned b0 = Vs[ks * 8 + t4    ][8 * ni + g];
                unsigned b1 = Vs[ks * 8 + t4 + 4][8 * ni + g];
                mma_tf32(o[ni], a0, a1, a2, a3, b0, b1);
            }
        }
        __syncwarp();
    }

    float inv0 = 1.0f / l0;
    float inv1 = 1.0f / l1;
    int grow = rbase + qt * 64 + prow;
    float* dst0 = &att[(size_t)grow * W + h * ROPE];
    float* dst1 = dst0 + (size_t)8 * W;
    #pragma unroll
    for (int ni = 0; ni < 4; ni++) {
        int col = 8 * ni + 2 * t4;
        *(float2*)&dst0[col] = make_float2(o[ni][0] * inv0, o[ni][1] * inv0);
        *(float2*)&dst1[col] = make_float2(o[ni][2] * inv1, o[ni][3] * inv1);
    }
}

// ---------------------------------------------------------------------------
// Launch
// ---------------------------------------------------------------------------
extern "C" void kernel_launch(void* const* d_in, const int* in_sizes, int n_in,
                              void* d_out, int out_size)
{
    const float* x   = (const float*)d_in[0];
    const float* Wq  = (const float*)d_in[1];
    const float* Wkv = (const float*)d_in[2];
    const float* Wk  = (const float*)d_in[3];
    const float* Wv  = (const float*)d_in[4];
    const float* Wo  = (const float*)d_in[5];
    const float* qg  = (const float*)d_in[6];
    const float* kg  = (const float*)d_in[7];
    float* out = (float*)d_out;

    float *pqr, *pkv, *pk, *pv, *patt, *pwop;
    cudaGetSymbolAddress((void**)&pqr,  g_qr);
    cudaGetSymbolAddress((void**)&pkv,  g_kv);
    cudaGetSymbolAddress((void**)&pk,   g_k);
    cudaGetSymbolAddress((void**)&pv,   g_v);
    cudaGetSymbolAddress((void**)&patt, g_att);
    cudaGetSymbolAddress((void**)&pwop, g_wop);

    pack_wo_kernel<<<(HH * ROPE * DD + 255) / 256, 256>>>(Wo, pwop);

    // q = rmsnorm(x @ Wq) fused -> qr (8192 x 512)
    gemm_tf32<2><<<dim3(DD / 128, ROWS / 128), 256>>>(ROWS, DD, DD, x, Wq, pqr, qg);
    // kv = x @ Wkv (8192,128,1024)
    gemm_tf32<0><<<dim3(LAT / 128, ROWS / 128), 256>>>(ROWS, LAT, DD, x, Wkv, pkv, nullptr);
    // k = rmsnorm(kv @ Wk) fused (8192,512,128)
    gemm_tf32<1><<<dim3((HH * ROPE) / 128, ROWS / 128), 256>>>(ROWS, HH * ROPE, LAT, pkv, Wk, pk, kg);
    // v = kv @ Wv
    gemm_tf32<0><<<dim3((HH * ROPE) / 128, ROWS / 128), 256>>>(ROWS, HH * ROPE, LAT, pkv, Wv, pv, nullptr);

    // tensor-core flash attention
    attn_mma_kernel<<<dim3(TT / 64, BB * HH), 128>>>(pqr, pk, pv, patt);

    // out = att @ WoP  (8192,1024,512)
    gemm_tf32<0><<<dim3(DD / 128, ROWS / 128), 256>>>(ROWS, DD, HH * ROPE, patt, pwop, out, nullptr);
}

// round 8
// speedup vs baseline: 3.0397x; 1.0209x over previous
#include <cuda_runtime.h>
#include <cuda_bf16.h>
#include <math.h>

// Problem constants
#define BB   4
#define TT   2048
#define DD   1024
#define HH   16
#define HD   64
#define LAT  128
#define ROPE 32
#define ROWS (BB*TT)          // 8192
#define EPSV 1e-6f

// Scratch
__device__ float g_qr [ROWS * HH * ROPE]; // normalized q (first 32 dims/head)
__device__ float g_kv [ROWS * LAT];
__device__ float g_k  [ROWS * HH * ROPE]; // normalized k
__device__ float g_v  [ROWS * HH * ROPE];
__device__ float g_att[ROWS * HH * ROPE];
__device__ float g_wop[HH * ROPE * DD];

// ---------------------------------------------------------------------------
// fp32 -> tf32 bits, round-to-nearest
// ---------------------------------------------------------------------------
__device__ __forceinline__ unsigned f2tf(float f) {
    unsigned u;
    asm("cvt.rna.tf32.f32 %0, %1;" : "=r"(u) : "f"(f));
    return u;
}

__device__ __forceinline__ void mma_tf32(
    float* c, unsigned a0, unsigned a1, unsigned a2, unsigned a3,
    unsigned b0, unsigned b1)
{
    asm volatile(
        "mma.sync.aligned.m16n8k8.row.col.f32.tf32.tf32.f32 "
        "{%0,%1,%2,%3}, {%4,%5,%6,%7}, {%8,%9}, {%0,%1,%2,%3};"
        : "+f"(c[0]), "+f"(c[1]), "+f"(c[2]), "+f"(c[3])
        : "r"(a0), "r"(a1), "r"(a2), "r"(a3), "r"(b0), "r"(b1));
}

// ---------------------------------------------------------------------------
// TF32 tensor-core GEMM, double-buffered smem pipeline (unchanged from R7).
// MODE 0 plain / MODE 1 fused K-RMSNorm / MODE 2 fused Q-RMSNorm
// ---------------------------------------------------------------------------
template<int MODE>
__global__ __launch_bounds__(256) void gemm_tf32(
    int M, int N, int K,
    const float* __restrict__ A, const float* __restrict__ B,
    float* __restrict__ C, const float* __restrict__ gvec)
{
    __shared__ unsigned As[2][128][20];
    __shared__ unsigned Bs[2][16][136];
    __shared__ float ssbuf[128][4];

    const int tid  = threadIdx.x;
    const int lane = tid & 31;
    const int warp = tid >> 5;
    const int g    = lane >> 2;
    const int t4   = lane & 3;
    const int wr   = warp >> 2;
    const int wc   = warp & 3;

    const int bM = blockIdx.y * 128;
    const int bN = blockIdx.x * 128;

    const int aRow = tid >> 2;
    const int aCol = (tid & 3) * 4;
    const int bRow = tid >> 5;
    const int bCol = (tid & 31) * 4;

    float acc[4][4][4];
    #pragma unroll
    for (int i = 0; i < 4; i++)
        #pragma unroll
        for (int j = 0; j < 4; j++)
            #pragma unroll
            for (int c = 0; c < 4; c++) acc[i][j][c] = 0.f;

    const float* Ab = A + (size_t)bM * K;
    const float* Bb = B + bN;

    float4 ra0, ra1, rb0, rb1;

    ra0 = *(const float4*)&Ab[(size_t)aRow * K + aCol];
    ra1 = *(const float4*)&Ab[(size_t)(aRow + 64) * K + aCol];
    rb0 = *(const float4*)&Bb[(size_t)bRow * N + bCol];
    rb1 = *(const float4*)&Bb[(size_t)(bRow + 8) * N + bCol];
    {
        As[0][aRow][aCol+0] = f2tf(ra0.x); As[0][aRow][aCol+1] = f2tf(ra0.y);
        As[0][aRow][aCol+2] = f2tf(ra0.z); As[0][aRow][aCol+3] = f2tf(ra0.w);
        As[0][aRow+64][aCol+0] = f2tf(ra1.x); As[0][aRow+64][aCol+1] = f2tf(ra1.y);
        As[0][aRow+64][aCol+2] = f2tf(ra1.z); As[0][aRow+64][aCol+3] = f2tf(ra1.w);
        uint4 u0 = make_uint4(f2tf(rb0.x), f2tf(rb0.y), f2tf(rb0.z), f2tf(rb0.w));
        uint4 u1 = make_uint4(f2tf(rb1.x), f2tf(rb1.y), f2tf(rb1.z), f2tf(rb1.w));
        *(uint4*)&Bs[0][bRow][bCol]     = u0;
        *(uint4*)&Bs[0][bRow + 8][bCol] = u1;
    }
    __syncthreads();

    const int nIter = K >> 4;
    for (int it = 0; it < nIter; it++) {
        const int p = it & 1;
        if (it + 1 < nIter) {
            int k0 = (it + 1) << 4;
            ra0 = *(const float4*)&Ab[(size_t)aRow * K + k0 + aCol];
            ra1 = *(const float4*)&Ab[(size_t)(aRow + 64) * K + k0 + aCol];
            rb0 = *(const float4*)&Bb[(size_t)(k0 + bRow) * N + bCol];
            rb1 = *(const float4*)&Bb[(size_t)(k0 + bRow + 8) * N + bCol];
        }

        #pragma unroll
        for (int kk = 0; kk < 16; kk += 8) {
            unsigned a[4][4], b[4][2];
            #pragma unroll
            for (int mi = 0; mi < 4; mi++) {
                int row = wr * 64 + mi * 16 + g;
                a[mi][0] = As[p][row    ][kk + t4];
                a[mi][1] = As[p][row + 8][kk + t4];
                a[mi][2] = As[p][row    ][kk + t4 + 4];
                a[mi][3] = As[p][row + 8][kk + t4 + 4];
            }
            #pragma unroll
            for (int ni = 0; ni < 4; ni++) {
                int col = wc * 32 + ni * 8 + g;
                b[ni][0] = Bs[p][kk + t4    ][col];
                b[ni][1] = Bs[p][kk + t4 + 4][col];
            }
            #pragma unroll
            for (int mi = 0; mi < 4; mi++)
                #pragma unroll
                for (int ni = 0; ni < 4; ni++)
                    mma_tf32(acc[mi][ni], a[mi][0], a[mi][1], a[mi][2], a[mi][3],
                             b[ni][0], b[ni][1]);
        }

        if (it + 1 < nIter) {
            const int q = p ^ 1;
            As[q][aRow][aCol+0] = f2tf(ra0.x); As[q][aRow][aCol+1] = f2tf(ra0.y);
            As[q][aRow][aCol+2] = f2tf(ra0.z); As[q][aRow][aCol+3] = f2tf(ra0.w);
            As[q][aRow+64][aCol+0] = f2tf(ra1.x); As[q][aRow+64][aCol+1] = f2tf(ra1.y);
            As[q][aRow+64][aCol+2] = f2tf(ra1.z); As[q][aRow+64][aCol+3] = f2tf(ra1.w);
            uint4 u0 = make_uint4(f2tf(rb0.x), f2tf(rb0.y), f2tf(rb0.z), f2tf(rb0.w));
            uint4 u1 = make_uint4(f2tf(rb1.x), f2tf(rb1.y), f2tf(rb1.z), f2tf(rb1.w));
            *(uint4*)&Bs[q][bRow][bCol]     = u0;
            *(uint4*)&Bs[q][bRow + 8][bCol] = u1;
        }
        __syncthreads();
    }

    if (MODE == 0) {
        #pragma unroll
        for (int mi = 0; mi < 4; mi++) {
            #pragma unroll
            for (int ni = 0; ni < 4; ni++) {
                int row = bM + wr * 64 + mi * 16 + g;
                int col = bN + wc * 32 + ni * 8 + 2 * t4;
                *(float2*)&C[(size_t)row * N + col] =
                    make_float2(acc[mi][ni][0], acc[mi][ni][1]);
                *(float2*)&C[(size_t)(row + 8) * N + col] =
                    make_float2(acc[mi][ni][2], acc[mi][ni][3]);
            }
        }
    } else if (MODE == 1) {
        #pragma unroll
        for (int mi = 0; mi < 4; mi++) {
            float ss0 = 0.f, ss1 = 0.f;
            #pragma unroll
            for (int ni = 0; ni < 4; ni++) {
                ss0 += acc[mi][ni][0]*acc[mi][ni][0] + acc[mi][ni][1]*acc[mi][ni][1];
                ss1 += acc[mi][ni][2]*acc[mi][ni][2] + acc[mi][ni][3]*acc[mi][ni][3];
            }
            ss0 += __shfl_xor_sync(0xffffffffu, ss0, 1);
            ss0 += __shfl_xor_sync(0xffffffffu, ss0, 2);
            ss1 += __shfl_xor_sync(0xffffffffu, ss1, 1);
            ss1 += __shfl_xor_sync(0xffffffffu, ss1, 2);
            float rinv0 = rsqrtf(ss0 * (1.0f / ROPE) + EPSV);
            float rinv1 = rsqrtf(ss1 * (1.0f / ROPE) + EPSV);
            int row = bM + wr * 64 + mi * 16 + g;
            #pragma unroll
            for (int ni = 0; ni < 4; ni++) {
                int d   = ni * 8 + 2 * t4;
                int col = bN + wc * 32 + d;
                float g0 = gvec[d], g1 = gvec[d + 1];
                *(float2*)&C[(size_t)row * N + col] =
                    make_float2(acc[mi][ni][0] * rinv0 * g0,
                                acc[mi][ni][1] * rinv0 * g1);
                *(float2*)&C[(size_t)(row + 8) * N + col] =
                    make_float2(acc[mi][ni][2] * rinv1 * g0,
                                acc[mi][ni][3] * rinv1 * g1);
            }
        }
    } else {
        #pragma unroll
        for (int mi = 0; mi < 4; mi++) {
            float ss0 = 0.f, ss1 = 0.f;
            #pragma unroll
            for (int ni = 0; ni < 4; ni++) {
                ss0 += acc[mi][ni][0]*acc[mi][ni][0] + acc[mi][ni][1]*acc[mi][ni][1];
                ss1 += acc[mi][ni][2]*acc[mi][ni][2] + acc[mi][ni][3]*acc[mi][ni][3];
            }
            ss0 += __shfl_xor_sync(0xffffffffu, ss0, 1);
            ss0 += __shfl_xor_sync(0xffffffffu, ss0, 2);
            ss1 += __shfl_xor_sync(0xffffffffu, ss1, 1);
            ss1 += __shfl_xor_sync(0xffffffffu, ss1, 2);
            if (t4 == 0) {
                int lr = wr * 64 + mi * 16 + g;
                ssbuf[lr][wc]     = ss0;
                ssbuf[lr + 8][wc] = ss1;
            }
        }
        __syncthreads();
        if ((wc & 1) == 0) {
            #pragma unroll
            for (int mi = 0; mi < 4; mi++) {
                int lr = wr * 64 + mi * 16 + g;
                float t0 = ssbuf[lr][wc] + ssbuf[lr][wc ^ 1];
                float t1 = ssbuf[lr + 8][wc] + ssbuf[lr + 8][wc ^ 1];
                float rinv0 = rsqrtf(t0 * (1.0f / HD) + EPSV);
                float rinv1 = rsqrtf(t1 * (1.0f / HD) + EPSV);
                int row = bM + lr;
                #pragma unroll
                for (int ni = 0; ni < 4; ni++) {
                    int d  = ni * 8 + 2 * t4;
                    int cg = bN + wc * 32 + d;
                    int qc = (cg >> 6) * 32 + d;
                    float g0 = gvec[d], g1 = gvec[d + 1];
                    *(float2*)&C[(size_t)row * 512 + qc] =
                        make_float2(acc[mi][ni][0] * rinv0 * g0,
                                    acc[mi][ni][1] * rinv0 * g1);
                    *(float2*)&C[(size_t)(row + 8) * 512 + qc] =
                        make_float2(acc[mi][ni][2] * rinv1 * g0,
                                    acc[mi][ni][3] * rinv1 * g1);
                }
            }
        }
    }
}

// ---------------------------------------------------------------------------
// Pack Wo
// ---------------------------------------------------------------------------
__global__ void pack_wo_kernel(const float* __restrict__ Wo, float* __restrict__ WoP)
{
    int idx = blockIdx.x * blockDim.x + threadIdx.x;
    if (idx >= HH * ROPE * DD) return;
    int r = idx >> 10;
    int n = idx & 1023;
    int h = r >> 5;
    int d = r & 31;
    WoP[idx] = Wo[(size_t)(h * HD + d) * DD + n];
}

// ---------------------------------------------------------------------------
// Tensor-core flash attention (causal), BQ=128 queries per CTA, 8 warps.
// Warp w owns query rows [16w,16w+16). Key tiles of 64, register-prefetched.
// Dynamic smem: QPs[128][68] | Ks[64][36] | Vs[64][40]  (54272 B)
// qt reversed so longest CTAs launch first.
// ---------------------------------------------------------------------------
#define ATTN_SMEM ((128*68 + 64*36 + 64*40) * 4)

__global__ __launch_bounds__(256) void attn_mma_kernel(
    const float* __restrict__ qr, const float* __restrict__ kk_,
    const float* __restrict__ vv, float* __restrict__ att)
{
    extern __shared__ unsigned smemraw[];
    unsigned (*QPs)[68] = (unsigned(*)[68])smemraw;                    // P / Q staging
    unsigned (*Ks )[36] = (unsigned(*)[36])(smemraw + 128 * 68);
    unsigned (*Vs )[40] = (unsigned(*)[40])(smemraw + 128 * 68 + 64 * 36);

    const int qt  = (gridDim.x - 1) - blockIdx.x;   // reversed: big CTAs first
    const int bh  = blockIdx.y;
    const int b   = bh >> 4;
    const int h   = bh & 15;
    const int tid = threadIdx.x;
    const int lane = tid & 31;
    const int w    = tid >> 5;          // 0..7
    const int g    = lane >> 2;
    const int t4   = lane & 3;
    const int rbase = b * TT;
    const int W = HH * ROPE;            // 512

    // ---- stage Q tile (128 x 32, fp32 bits) ----
    for (int f = tid; f < 128 * 8; f += 256) {
        int row = f >> 3, c4 = (f & 7) * 4;
        float4 v = *(const float4*)&qr[(size_t)(rbase + qt * 128 + row) * W + h * ROPE + c4];
        QPs[row][c4 + 0] = __float_as_uint(v.x);
        QPs[row][c4 + 1] = __float_as_uint(v.y);
        QPs[row][c4 + 2] = __float_as_uint(v.z);
        QPs[row][c4 + 3] = __float_as_uint(v.w);
    }
    __syncthreads();

    const int prow = w * 16 + g;        // 0..127
    unsigned aq[4][4];
    #pragma unroll
    for (int ks = 0; ks < 4; ks++) {
        aq[ks][0] = f2tf(0.125f * __uint_as_float(QPs[prow    ][ks * 8 + t4]));
        aq[ks][1] = f2tf(0.125f * __uint_as_float(QPs[prow + 8][ks * 8 + t4]));
        aq[ks][2] = f2tf(0.125f * __uint_as_float(QPs[prow    ][ks * 8 + t4 + 4]));
        aq[ks][3] = f2tf(0.125f * __uint_as_float(QPs[prow + 8][ks * 8 + t4 + 4]));
    }
    // (P writes below only touch warp w's own 16-row stripe, already consumed)

    float m0 = -INFINITY, m1 = -INFINITY, l0 = 0.f, l1 = 0.f;
    float o[4][4];
    #pragma unroll
    for (int ni = 0; ni < 4; ni++)
        #pragma unroll
        for (int c = 0; c < 4; c++) o[ni][c] = 0.f;

    // K/V prefetch: 512 float4 per array per tile; 256 threads -> 2 each
    const int pfRow0 = tid >> 3;                 // 0..31
    const int pfRow1 = (tid >> 3) + 32;          // 32..63
    const int pfC4   = (tid & 7) * 4;

    const int nkt = 2 * qt + 2;                  // key tiles (64 keys each)

    // prologue: prefetch tile 0
    float4 rk0, rk1, rv0, rv1;
    {
        size_t g0 = (size_t)(rbase + pfRow0) * W + h * ROPE + pfC4;
        size_t g1 = (size_t)(rbase + pfRow1) * W + h * ROPE + pfC4;
        rk0 = *(const float4*)&kk_[g0];
        rk1 = *(const float4*)&kk_[g1];
        rv0 = *(const float4*)&vv[g0];
        rv1 = *(const float4*)&vv[g1];
    }

    for (int kt = 0; kt < nkt; kt++) {
        // store prefetched tile to smem (tf32)
        Ks[pfRow0][pfC4+0] = f2tf(rk0.x); Ks[pfRow0][pfC4+1] = f2tf(rk0.y);
        Ks[pfRow0][pfC4+2] = f2tf(rk0.z); Ks[pfRow0][pfC4+3] = f2tf(rk0.w);
        Ks[pfRow1][pfC4+0] = f2tf(rk1.x); Ks[pfRow1][pfC4+1] = f2tf(rk1.y);
        Ks[pfRow1][pfC4+2] = f2tf(rk1.z); Ks[pfRow1][pfC4+3] = f2tf(rk1.w);
        Vs[pfRow0][pfC4+0] = f2tf(rv0.x); Vs[pfRow0][pfC4+1] = f2tf(rv0.y);
        Vs[pfRow0][pfC4+2] = f2tf(rv0.z); Vs[pfRow0][pfC4+3] = f2tf(rv0.w);
        Vs[pfRow1][pfC4+0] = f2tf(rv1.x); Vs[pfRow1][pfC4+1] = f2tf(rv1.y);
        Vs[pfRow1][pfC4+2] = f2tf(rv1.z); Vs[pfRow1][pfC4+3] = f2tf(rv1.w);
        __syncthreads();

        // prefetch next tile (LDG latency hidden behind mma/softmax below)
        if (kt + 1 < nkt) {
            size_t g0 = (size_t)(rbase + (kt + 1) * 64 + pfRow0) * W + h * ROPE + pfC4;
            size_t g1 = (size_t)(rbase + (kt + 1) * 64 + pfRow1) * W + h * ROPE + pfC4;
            rk0 = *(const float4*)&kk_[g0];
            rk1 = *(const float4*)&kk_[g1];
            rv0 = *(const float4*)&vv[g0];
            rv1 = *(const float4*)&vv[g1];
        }

        // S = Q @ K^T : 8 n-tiles x 4 k-steps
        float s[8][4];
        #pragma unroll
        for (int j = 0; j < 8; j++)
            #pragma unroll
            for (int c = 0; c < 4; c++) s[j][c] = 0.f;

        #pragma unroll
        for (int ks = 0; ks < 4; ks++) {
            #pragma unroll
            for (int j = 0; j < 8; j++) {
                unsigned b0 = Ks[8 * j + g][ks * 8 + t4];
                unsigned b1 = Ks[8 * j + g][ks * 8 + t4 + 4];
                mma_tf32(s[j], aq[ks][0], aq[ks][1], aq[ks][2], aq[ks][3], b0, b1);
            }
        }

        // causal mask: key_global > query_global, only possible on last 2 tiles
        if (kt >= 2 * qt) {
            int off = (kt - 2 * qt) * 64;   // 0 or 64
            #pragma unroll
            for (int j = 0; j < 8; j++) {
                int cl = off + 8 * j + 2 * t4;
                if (cl     > prow    ) s[j][0] = -INFINITY;
                if (cl + 1 > prow    ) s[j][1] = -INFINITY;
                if (cl     > prow + 8) s[j][2] = -INFINITY;
                if (cl + 1 > prow + 8) s[j][3] = -INFINITY;
            }
        }

        // online softmax
        float mx0 = m0, mx1 = m1;
        #pragma unroll
        for (int j = 0; j < 8; j++) {
            mx0 = fmaxf(mx0, fmaxf(s[j][0], s[j][1]));
            mx1 = fmaxf(mx1, fmaxf(s[j][2], s[j][3]));
        }
        mx0 = fmaxf(mx0, __shfl_xor_sync(0xffffffffu, mx0, 1));
        mx0 = fmaxf(mx0, __shfl_xor_sync(0xffffffffu, mx0, 2));
        mx1 = fmaxf(mx1, __shfl_xor_sync(0xffffffffu, mx1, 1));
        mx1 = fmaxf(mx1, __shfl_xor_sync(0xffffffffu, mx1, 2));

        float sc0 = __expf(m0 - mx0);
        float sc1 = __expf(m1 - mx1);
        m0 = mx0; m1 = mx1;

        float ls0 = 0.f, ls1 = 0.f;
        #pragma unroll
        for (int j = 0; j < 8; j++) {
            float p0 = __expf(s[j][0] - m0);
            float p1 = __expf(s[j][1] - m0);
            float p2 = __expf(s[j][2] - m1);
            float p3 = __expf(s[j][3] - m1);
            ls0 += p0 + p1;
            ls1 += p2 + p3;
            QPs[prow    ][8 * j + 2 * t4    ] = f2tf(p0);
            QPs[prow    ][8 * j + 2 * t4 + 1] = f2tf(p1);
            QPs[prow + 8][8 * j + 2 * t4    ] = f2tf(p2);
            QPs[prow + 8][8 * j + 2 * t4 + 1] = f2tf(p3);
        }
        ls0 += __shfl_xor_sync(0xffffffffu, ls0, 1);
        ls0 += __shfl_xor_sync(0xffffffffu, ls0, 2);
        ls1 += __shfl_xor_sync(0xffffffffu, ls1, 1);
        ls1 += __shfl_xor_sync(0xffffffffu, ls1, 2);
        l0 = l0 * sc0 + ls0;
        l1 = l1 * sc1 + ls1;

        #pragma unroll
        for (int ni = 0; ni < 4; ni++) {
            o[ni][0] *= sc0; o[ni][1] *= sc0;
            o[ni][2] *= sc1; o[ni][3] *= sc1;
        }
        __syncwarp();

        // O += P @ V : 4 n-tiles x 8 k-steps
        #pragma unroll
        for (int ks = 0; ks < 8; ks++) {
            unsigned a0 = QPs[prow    ][ks * 8 + t4];
            unsigned a1 = QPs[prow + 8][ks * 8 + t4];
            unsigned a2 = QPs[prow    ][ks * 8 + t4 + 4];
            unsigned a3 = QPs[prow + 8][ks * 8 + t4 + 4];
            #pragma unroll
            for (int ni = 0; ni < 4; ni++) {
                unsigned b0 = Vs[ks * 8 + t4    ][8 * ni + g];
                unsigned b1 = Vs[ks * 8 + t4 + 4][8 * ni + g];
                mma_tf32(o[ni], a0, a1, a2, a3, b0, b1);
            }
        }
        __syncthreads();   // all warps done with Ks/Vs before next store
    }

    // epilogue
    float inv0 = 1.0f / l0;
    float inv1 = 1.0f / l1;
    int grow = rbase + qt * 128 + prow;
    float* dst0 = &att[(size_t)grow * W + h * ROPE];
    float* dst1 = dst0 + (size_t)8 * W;
    #pragma unroll
    for (int ni = 0; ni < 4; ni++) {
        int col = 8 * ni + 2 * t4;
        *(float2*)&dst0[col] = make_float2(o[ni][0] * inv0, o[ni][1] * inv0);
        *(float2*)&dst1[col] = make_float2(o[ni][2] * inv1, o[ni][3] * inv1);
    }
}

// ---------------------------------------------------------------------------
// Launch
// ---------------------------------------------------------------------------
extern "C" void kernel_launch(void* const* d_in, const int* in_sizes, int n_in,
                              void* d_out, int out_size)
{
    const float* x   = (const float*)d_in[0];
    const float* Wq  = (const float*)d_in[1];
    const float* Wkv = (const float*)d_in[2];
    const float* Wk  = (const float*)d_in[3];
    const float* Wv  = (const float*)d_in[4];
    const float* Wo  = (const float*)d_in[5];
    const float* qg  = (const float*)d_in[6];
    const float* kg  = (const float*)d_in[7];
    float* out = (float*)d_out;

    float *pqr, *pkv, *pk, *pv, *patt, *pwop;
    cudaGetSymbolAddress((void**)&pqr,  g_qr);
    cudaGetSymbolAddress((void**)&pkv,  g_kv);
    cudaGetSymbolAddress((void**)&pk,   g_k);
    cudaGetSymbolAddress((void**)&pv,   g_v);
    cudaGetSymbolAddress((void**)&patt, g_att);
    cudaGetSymbolAddress((void**)&pwop, g_wop);

    cudaFuncSetAttribute(attn_mma_kernel,
                         cudaFuncAttributeMaxDynamicSharedMemorySize, ATTN_SMEM);

    pack_wo_kernel<<<(HH * ROPE * DD + 255) / 256, 256>>>(Wo, pwop);

    // q = rmsnorm(x @ Wq) fused -> qr (8192 x 512)
    gemm_tf32<2><<<dim3(DD / 128, ROWS / 128), 256>>>(ROWS, DD, DD, x, Wq, pqr, qg);
    // kv = x @ Wkv (8192,128,1024)
    gemm_tf32<0><<<dim3(LAT / 128, ROWS / 128), 256>>>(ROWS, LAT, DD, x, Wkv, pkv, nullptr);
    // k = rmsnorm(kv @ Wk) fused (8192,512,128)
    gemm_tf32<1><<<dim3((HH * ROPE) / 128, ROWS / 128), 256>>>(ROWS, HH * ROPE, LAT, pkv, Wk, pk, kg);
    // v = kv @ Wv
    gemm_tf32<0><<<dim3((HH * ROPE) / 128, ROWS / 128), 256>>>(ROWS, HH * ROPE, LAT, pkv, Wv, pv, nullptr);

    // tensor-core flash attention (BQ=128, reversed qt)
    attn_mma_kernel<<<dim3(TT / 128, BB * HH), 256, ATTN_SMEM>>>(pqr, pk, pv, patt);

    // out = att @ WoP  (8192,1024,512)
    gemm_tf32<0><<<dim3(DD / 128, ROWS / 128), 256>>>(ROWS, DD, HH * ROPE, patt, pwop, out, nullptr);
}

// round 9
// speedup vs baseline: 3.1811x; 1.0465x over previous
#include <cuda_runtime.h>
#include <cuda_bf16.h>
#include <math.h>

// Problem constants
#define BB   4
#define TT   2048
#define DD   1024
#define HH   16
#define HD   64
#define LAT  128
#define ROPE 32
#define ROWS (BB*TT)          // 8192
#define EPSV 1e-6f
#define KVSPLIT 4

// Scratch
__device__ float g_qr [ROWS * HH * ROPE];
__device__ float g_kv [ROWS * LAT];
__device__ float g_kvp[KVSPLIT * ROWS * LAT];   // split-K partials
__device__ float g_k  [ROWS * HH * ROPE];
__device__ float g_v  [ROWS * HH * ROPE];
__device__ float g_att[ROWS * HH * ROPE];
__device__ float g_wop[HH * ROPE * DD];

// ---------------------------------------------------------------------------
// fp32 -> tf32 bits, round-to-nearest
// ---------------------------------------------------------------------------
__device__ __forceinline__ unsigned f2tf(float f) {
    unsigned u;
    asm("cvt.rna.tf32.f32 %0, %1;" : "=r"(u) : "f"(f));
    return u;
}

__device__ __forceinline__ void mma_tf32(
    float* c, unsigned a0, unsigned a1, unsigned a2, unsigned a3,
    unsigned b0, unsigned b1)
{
    asm volatile(
        "mma.sync.aligned.m16n8k8.row.col.f32.tf32.tf32.f32 "
        "{%0,%1,%2,%3}, {%4,%5,%6,%7}, {%8,%9}, {%0,%1,%2,%3};"
        : "+f"(c[0]), "+f"(c[1]), "+f"(c[2]), "+f"(c[3])
        : "r"(a0), "r"(a1), "r"(a2), "r"(a3), "r"(b0), "r"(b1));
}

// A-tile column permutation: k and k+4 stored adjacently so a-fragment
// loads become LDS.64.  pos(c) = 2*(c&3) | ((c>>2)&1) | (c&8)
__device__ __forceinline__ int apos(int c) {
    return ((c & 3) << 1) | ((c >> 2) & 1) | (c & 8);
}

// ---------------------------------------------------------------------------
// TF32 tensor-core GEMM, double-buffered, k-interleaved A fragments.
// C[M,N] = A[M,K] @ B[K,N] (row-major, lda = A row stride).
// MODE 0 plain / MODE 1 fused K-RMSNorm / MODE 2 fused Q-RMSNorm /
// MODE 3 split-K partials (blockIdx.x = k-chunk, N col tiles must == 1)
// ---------------------------------------------------------------------------
template<int MODE>
__global__ __launch_bounds__(256) void gemm_tf32(
    int M, int N, int K, int lda,
    const float* __restrict__ A, const float* __restrict__ B,
    float* __restrict__ C, const float* __restrict__ gvec)
{
    __shared__ unsigned As[2][128][24];    // k-interleaved, stride 24 (bank-clean)
    __shared__ unsigned Bs[2][16][136];
    __shared__ float ssbuf[128][4];

    const int tid  = threadIdx.x;
    const int lane = tid & 31;
    const int warp = tid >> 5;
    const int g    = lane >> 2;
    const int t4   = lane & 3;
    const int wr   = warp >> 2;
    const int wc   = warp & 3;

    const int bM = blockIdx.y * 128;
    const int bN = (MODE == 3) ? 0 : blockIdx.x * 128;

    // split-K chunk offsets
    const float* Ap = A;
    const float* Bp = B;
    float*       Cp = C;
    if (MODE == 3) {
        Ap += (size_t)blockIdx.x * K;            // K = chunk size
        Bp += (size_t)blockIdx.x * K * N;
        Cp += (size_t)blockIdx.x * M * N;
    }

    const int aRow = tid >> 2;
    const int aCol = (tid & 3) * 4;
    const int bRow = tid >> 5;
    const int bCol = (tid & 31) * 4;

    // precompute A store positions for the 4 staged words
    const int ap0 = apos(aCol + 0), ap1 = apos(aCol + 1);
    const int ap2 = apos(aCol + 2), ap3 = apos(aCol + 3);

    float acc[4][4][4];
    #pragma unroll
    for (int i = 0; i < 4; i++)
        #pragma unroll
        for (int j = 0; j < 4; j++)
            #pragma unroll
            for (int c = 0; c < 4; c++) acc[i][j][c] = 0.f;

    const float* Ab = Ap + (size_t)bM * lda;
    const float* Bb = Bp + bN;

    float4 ra0, ra1, rb0, rb1;

    ra0 = *(const float4*)&Ab[(size_t)aRow * lda + aCol];
    ra1 = *(const float4*)&Ab[(size_t)(aRow + 64) * lda + aCol];
    rb0 = *(const float4*)&Bb[(size_t)bRow * N + bCol];
    rb1 = *(const float4*)&Bb[(size_t)(bRow + 8) * N + bCol];
    {
        As[0][aRow][ap0] = f2tf(ra0.x); As[0][aRow][ap1] = f2tf(ra0.y);
        As[0][aRow][ap2] = f2tf(ra0.z); As[0][aRow][ap3] = f2tf(ra0.w);
        As[0][aRow+64][ap0] = f2tf(ra1.x); As[0][aRow+64][ap1] = f2tf(ra1.y);
        As[0][aRow+64][ap2] = f2tf(ra1.z); As[0][aRow+64][ap3] = f2tf(ra1.w);
        uint4 u0 = make_uint4(f2tf(rb0.x), f2tf(rb0.y), f2tf(rb0.z), f2tf(rb0.w));
        uint4 u1 = make_uint4(f2tf(rb1.x), f2tf(rb1.y), f2tf(rb1.z), f2tf(rb1.w));
        *(uint4*)&Bs[0][bRow][bCol]     = u0;
        *(uint4*)&Bs[0][bRow + 8][bCol] = u1;
    }
    __syncthreads();

    const int nIter = K >> 4;
    for (int it = 0; it < nIter; it++) {
        const int p = it & 1;
        if (it + 1 < nIter) {
            int k0 = (it + 1) << 4;
            ra0 = *(const float4*)&Ab[(size_t)aRow * lda + k0 + aCol];
            ra1 = *(const float4*)&Ab[(size_t)(aRow + 64) * lda + k0 + aCol];
            rb0 = *(const float4*)&Bb[(size_t)(k0 + bRow) * N + bCol];
            rb1 = *(const float4*)&Bb[(size_t)(k0 + bRow + 8) * N + bCol];
        }

        #pragma unroll
        for (int kb = 0; kb < 2; kb++) {
            const int kk = kb * 8;
            unsigned a[4][4], b[4][2];
            #pragma unroll
            for (int mi = 0; mi < 4; mi++) {
                int row = wr * 64 + mi * 16 + g;
                uint2 uA0 = *(const uint2*)&As[p][row    ][kk + 2 * t4]; // a0,a2
                uint2 uA1 = *(const uint2*)&As[p][row + 8][kk + 2 * t4]; // a1,a3
                a[mi][0] = uA0.x; a[mi][1] = uA1.x;
                a[mi][2] = uA0.y; a[mi][3] = uA1.y;
            }
            #pragma unroll
            for (int ni = 0; ni < 4; ni++) {
                int col = wc * 32 + ni * 8 + g;
                b[ni][0] = Bs[p][kk + t4    ][col];
                b[ni][1] = Bs[p][kk + t4 + 4][col];
            }
            #pragma unroll
            for (int mi = 0; mi < 4; mi++)
                #pragma unroll
                for (int ni = 0; ni < 4; ni++)
                    mma_tf32(acc[mi][ni], a[mi][0], a[mi][1], a[mi][2], a[mi][3],
                             b[ni][0], b[ni][1]);
        }

        if (it + 1 < nIter) {
            const int q = p ^ 1;
            As[q][aRow][ap0] = f2tf(ra0.x); As[q][aRow][ap1] = f2tf(ra0.y);
            As[q][aRow][ap2] = f2tf(ra0.z); As[q][aRow][ap3] = f2tf(ra0.w);
            As[q][aRow+64][ap0] = f2tf(ra1.x); As[q][aRow+64][ap1] = f2tf(ra1.y);
            As[q][aRow+64][ap2] = f2tf(ra1.z); As[q][aRow+64][ap3] = f2tf(ra1.w);
            uint4 u0 = make_uint4(f2tf(rb0.x), f2tf(rb0.y), f2tf(rb0.z), f2tf(rb0.w));
            uint4 u1 = make_uint4(f2tf(rb1.x), f2tf(rb1.y), f2tf(rb1.z), f2tf(rb1.w));
            *(uint4*)&Bs[q][bRow][bCol]     = u0;
            *(uint4*)&Bs[q][bRow + 8][bCol] = u1;
        }
        __syncthreads();
    }

    if (MODE == 0 || MODE == 3) {
        #pragma unroll
        for (int mi = 0; mi < 4; mi++) {
            #pragma unroll
            for (int ni = 0; ni < 4; ni++) {
                int row = bM + wr * 64 + mi * 16 + g;
                int col = bN + wc * 32 + ni * 8 + 2 * t4;
                *(float2*)&Cp[(size_t)row * N + col] =
                    make_float2(acc[mi][ni][0], acc[mi][ni][1]);
                *(float2*)&Cp[(size_t)(row + 8) * N + col] =
                    make_float2(acc[mi][ni][2], acc[mi][ni][3]);
            }
        }
    } else if (MODE == 1) {
        #pragma unroll
        for (int mi = 0; mi < 4; mi++) {
            float ss0 = 0.f, ss1 = 0.f;
            #pragma unroll
            for (int ni = 0; ni < 4; ni++) {
                ss0 += acc[mi][ni][0]*acc[mi][ni][0] + acc[mi][ni][1]*acc[mi][ni][1];
                ss1 += acc[mi][ni][2]*acc[mi][ni][2] + acc[mi][ni][3]*acc[mi][ni][3];
            }
            ss0 += __shfl_xor_sync(0xffffffffu, ss0, 1);
            ss0 += __shfl_xor_sync(0xffffffffu, ss0, 2);
            ss1 += __shfl_xor_sync(0xffffffffu, ss1, 1);
            ss1 += __shfl_xor_sync(0xffffffffu, ss1, 2);
            float rinv0 = rsqrtf(ss0 * (1.0f / ROPE) + EPSV);
            float rinv1 = rsqrtf(ss1 * (1.0f / ROPE) + EPSV);
            int row = bM + wr * 64 + mi * 16 + g;
            #pragma unroll
            for (int ni = 0; ni < 4; ni++) {
                int d   = ni * 8 + 2 * t4;
                int col = bN + wc * 32 + d;
                float g0 = gvec[d], g1 = gvec[d + 1];
                *(float2*)&Cp[(size_t)row * N + col] =
                    make_float2(acc[mi][ni][0] * rinv0 * g0,
                                acc[mi][ni][1] * rinv0 * g1);
                *(float2*)&Cp[(size_t)(row + 8) * N + col] =
                    make_float2(acc[mi][ni][2] * rinv1 * g0,
                                acc[mi][ni][3] * rinv1 * g1);
            }
        }
    } else {
        #pragma unroll
        for (int mi = 0; mi < 4; mi++) {
            float ss0 = 0.f, ss1 = 0.f;
            #pragma unroll
            for (int ni = 0; ni < 4; ni++) {
                ss0 += acc[mi][ni][0]*acc[mi][ni][0] + acc[mi][ni][1]*acc[mi][ni][1];
                ss1 += acc[mi][ni][2]*acc[mi][ni][2] + acc[mi][ni][3]*acc[mi][ni][3];
            }
            ss0 += __shfl_xor_sync(0xffffffffu, ss0, 1);
            ss0 += __shfl_xor_sync(0xffffffffu, ss0, 2);
            ss1 += __shfl_xor_sync(0xffffffffu, ss1, 1);
            ss1 += __shfl_xor_sync(0xffffffffu, ss1, 2);
            if (t4 == 0) {
                int lr = wr * 64 + mi * 16 + g;
                ssbuf[lr][wc]     = ss0;
                ssbuf[lr + 8][wc] = ss1;
            }
        }
        __syncthreads();
        if ((wc & 1) == 0) {
            #pragma unroll
            for (int mi = 0; mi < 4; mi++) {
                int lr = wr * 64 + mi * 16 + g;
                float t0 = ssbuf[lr][wc] + ssbuf[lr][wc ^ 1];
                float t1 = ssbuf[lr + 8][wc] + ssbuf[lr + 8][wc ^ 1];
                float rinv0 = rsqrtf(t0 * (1.0f / HD) + EPSV);
                float rinv1 = rsqrtf(t1 * (1.0f / HD) + EPSV);
                int row = bM + lr;
                #pragma unroll
                for (int ni = 0; ni < 4; ni++) {
                    int d  = ni * 8 + 2 * t4;
                    int cg = bN + wc * 32 + d;
                    int qc = (cg >> 6) * 32 + d;
                    float g0 = gvec[d], g1 = gvec[d + 1];
                    *(float2*)&Cp[(size_t)row * 512 + qc] =
                        make_float2(acc[mi][ni][0] * rinv0 * g0,
                                    acc[mi][ni][1] * rinv0 * g1);
                    *(float2*)&Cp[(size_t)(row + 8) * 512 + qc] =
                        make_float2(acc[mi][ni][2] * rinv1 * g0,
                                    acc[mi][ni][3] * rinv1 * g1);
                }
            }
        }
    }
}

// ---------------------------------------------------------------------------
// kv split-K reduce: g_kv = sum of KVSPLIT partials (float4 vectorized)
// ---------------------------------------------------------------------------
__global__ void kv_reduce_kernel(const float* __restrict__ parts,
                                 float* __restrict__ kv)
{
    int i = (blockIdx.x * blockDim.x + threadIdx.x) * 4;
    if (i >= ROWS * LAT) return;
    const int STRIDE = ROWS * LAT;
    float4 s = *(const float4*)&parts[i];
    #pragma unroll
    for (int c = 1; c < KVSPLIT; c++) {
        float4 p = *(const float4*)&parts[c * STRIDE + i];
        s.x += p.x; s.y += p.y; s.z += p.z; s.w += p.w;
    }
    *(float4*)&kv[i] = s;
}

// ---------------------------------------------------------------------------
// Pack Wo
// ---------------------------------------------------------------------------
__global__ void pack_wo_kernel(const float* __restrict__ Wo, float* __restrict__ WoP)
{
    int idx = blockIdx.x * blockDim.x + threadIdx.x;
    if (idx >= HH * ROPE * DD) return;
    int r = idx >> 10;
    int n = idx & 1023;
    int h = r >> 5;
    int d = r & 31;
    WoP[idx] = Wo[(size_t)(h * HD + d) * DD + n];
}

// ---------------------------------------------------------------------------
// Tensor-core flash attention (causal), BQ=128, 8 warps (unchanged from R8).
// ---------------------------------------------------------------------------
#define ATTN_SMEM ((128*68 + 64*36 + 64*40) * 4)

__global__ __launch_bounds__(256) void attn_mma_kernel(
    const float* __restrict__ qr, const float* __restrict__ kk_,
    const float* __restrict__ vv, float* __restrict__ att)
{
    extern __shared__ unsigned smemraw[];
    unsigned (*QPs)[68] = (unsigned(*)[68])smemraw;
    unsigned (*Ks )[36] = (unsigned(*)[36])(smemraw + 128 * 68);
    unsigned (*Vs )[40] = (unsigned(*)[40])(smemraw + 128 * 68 + 64 * 36);

    const int qt  = (gridDim.x - 1) - blockIdx.x;
    const int bh  = blockIdx.y;
    const int b   = bh >> 4;
    const int h   = bh & 15;
    const int tid = threadIdx.x;
    const int lane = tid & 31;
    const int w    = tid >> 5;
    const int g    = lane >> 2;
    const int t4   = lane & 3;
    const int rbase = b * TT;
    const int W = HH * ROPE;

    for (int f = tid; f < 128 * 8; f += 256) {
        int row = f >> 3, c4 = (f & 7) * 4;
        float4 v = *(const float4*)&qr[(size_t)(rbase + qt * 128 + row) * W + h * ROPE + c4];
        QPs[row][c4 + 0] = __float_as_uint(v.x);
        QPs[row][c4 + 1] = __float_as_uint(v.y);
        QPs[row][c4 + 2] = __float_as_uint(v.z);
        QPs[row][c4 + 3] = __float_as_uint(v.w);
    }
    __syncthreads();

    const int prow = w * 16 + g;
    unsigned aq[4][4];
    #pragma unroll
    for (int ks = 0; ks < 4; ks++) {
        aq[ks][0] = f2tf(0.125f * __uint_as_float(QPs[prow    ][ks * 8 + t4]));
        aq[ks][1] = f2tf(0.125f * __uint_as_float(QPs[prow + 8][ks * 8 + t4]));
        aq[ks][2] = f2tf(0.125f * __uint_as_float(QPs[prow    ][ks * 8 + t4 + 4]));
        aq[ks][3] = f2tf(0.125f * __uint_as_float(QPs[prow + 8][ks * 8 + t4 + 4]));
    }

    float m0 = -INFINITY, m1 = -INFINITY, l0 = 0.f, l1 = 0.f;
    float o[4][4];
    #pragma unroll
    for (int ni = 0; ni < 4; ni++)
        #pragma unroll
        for (int c = 0; c < 4; c++) o[ni][c] = 0.f;

    const int pfRow0 = tid >> 3;
    const int pfRow1 = (tid >> 3) + 32;
    const int pfC4   = (tid & 7) * 4;

    const int nkt = 2 * qt + 2;

    float4 rk0, rk1, rv0, rv1;
    {
        size_t g0 = (size_t)(rbase + pfRow0) * W + h * ROPE + pfC4;
        size_t g1 = (size_t)(rbase + pfRow1) * W + h * ROPE + pfC4;
        rk0 = *(const float4*)&kk_[g0];
        rk1 = *(const float4*)&kk_[g1];
        rv0 = *(const float4*)&vv[g0];
        rv1 = *(const float4*)&vv[g1];
    }

    for (int kt = 0; kt < nkt; kt++) {
        Ks[pfRow0][pfC4+0] = f2tf(rk0.x); Ks[pfRow0][pfC4+1] = f2tf(rk0.y);
        Ks[pfRow0][pfC4+2] = f2tf(rk0.z); Ks[pfRow0][pfC4+3] = f2tf(rk0.w);
        Ks[pfRow1][pfC4+0] = f2tf(rk1.x); Ks[pfRow1][pfC4+1] = f2tf(rk1.y);
        Ks[pfRow1][pfC4+2] = f2tf(rk1.z); Ks[pfRow1][pfC4+3] = f2tf(rk1.w);
        Vs[pfRow0][pfC4+0] = f2tf(rv0.x); Vs[pfRow0][pfC4+1] = f2tf(rv0.y);
        Vs[pfRow0][pfC4+2] = f2tf(rv0.z); Vs[pfRow0][pfC4+3] = f2tf(rv0.w);
        Vs[pfRow1][pfC4+0] = f2tf(rv1.x); Vs[pfRow1][pfC4+1] = f2tf(rv1.y);
        Vs[pfRow1][pfC4+2] = f2tf(rv1.z); Vs[pfRow1][pfC4+3] = f2tf(rv1.w);
        __syncthreads();

        if (kt + 1 < nkt) {
            size_t g0 = (size_t)(rbase + (kt + 1) * 64 + pfRow0) * W + h * ROPE + pfC4;
            size_t g1 = (size_t)(rbase + (kt + 1) * 64 + pfRow1) * W + h * ROPE + pfC4;
            rk0 = *(const float4*)&kk_[g0];
            rk1 = *(const float4*)&kk_[g1];
            rv0 = *(const float4*)&vv[g0];
            rv1 = *(const float4*)&vv[g1];
        }

        float s[8][4];
        #pragma unroll
        for (int j = 0; j < 8; j++)
            #pragma unroll
            for (int c = 0; c < 4; c++) s[j][c] = 0.f;

        #pragma unroll
        for (int ks = 0; ks < 4; ks++) {
            #pragma unroll
            for (int j = 0; j < 8; j++) {
                unsigned b0 = Ks[8 * j + g][ks * 8 + t4];
                unsigned b1 = Ks[8 * j + g][ks * 8 + t4 + 4];
                mma_tf32(s[j], aq[ks][0], aq[ks][1], aq[ks][2], aq[ks][3], b0, b1);
            }
        }

        if (kt >= 2 * qt) {
            int off = (kt - 2 * qt) * 64;
            #pragma unroll
            for (int j = 0; j < 8; j++) {
                int cl = off + 8 * j + 2 * t4;
                if (cl     > prow    ) s[j][0] = -INFINITY;
                if (cl + 1 > prow    ) s[j][1] = -INFINITY;
                if (cl     > prow + 8) s[j][2] = -INFINITY;
                if (cl + 1 > prow + 8) s[j][3] = -INFINITY;
            }
        }

        float mx0 = m0, mx1 = m1;
        #pragma unroll
        for (int j = 0; j < 8; j++) {
            mx0 = fmaxf(mx0, fmaxf(s[j][0], s[j][1]));
            mx1 = fmaxf(mx1, fmaxf(s[j][2], s[j][3]));
        }
        mx0 = fmaxf(mx0, __shfl_xor_sync(0xffffffffu, mx0, 1));
        mx0 = fmaxf(mx0, __shfl_xor_sync(0xffffffffu, mx0, 2));
        mx1 = fmaxf(mx1, __shfl_xor_sync(0xffffffffu, mx1, 1));
        mx1 = fmaxf(mx1, __shfl_xor_sync(0xffffffffu, mx1, 2));

        float sc0 = __expf(m0 - mx0);
        float sc1 = __expf(m1 - mx1);
        m0 = mx0; m1 = mx1;

        float ls0 = 0.f, ls1 = 0.f;
        #pragma unroll
        for (int j = 0; j < 8; j++) {
            float p0 = __expf(s[j][0] - m0);
            float p1 = __expf(s[j][1] - m0);
            float p2 = __expf(s[j][2] - m1);
            float p3 = __expf(s[j][3] - m1);
            ls0 += p0 + p1;
            ls1 += p2 + p3;
            QPs[prow    ][8 * j + 2 * t4    ] = f2tf(p0);
            QPs[prow    ][8 * j + 2 * t4 + 1] = f2tf(p1);
            QPs[prow + 8][8 * j + 2 * t4    ] = f2tf(p2);
            QPs[prow + 8][8 * j + 2 * t4 + 1] = f2tf(p3);
        }
        ls0 += __shfl_xor_sync(0xffffffffu, ls0, 1);
        ls0 += __shfl_xor_sync(0xffffffffu, ls0, 2);
        ls1 += __shfl_xor_sync(0xffffffffu, ls1, 1);
        ls1 += __shfl_xor_sync(0xffffffffu, ls1, 2);
        l0 = l0 * sc0 + ls0;
        l1 = l1 * sc1 + ls1;

        #pragma unroll
        for (int ni = 0; ni < 4; ni++) {
            o[ni][0] *= sc0; o[ni][1] *= sc0;
            o[ni][2] *= sc1; o[ni][3] *= sc1;
        }
        __syncwarp();

        #pragma unroll
        for (int ks = 0; ks < 8; ks++) {
            unsigned a0 = QPs[prow    ][ks * 8 + t4];
            unsigned a1 = QPs[prow + 8][ks * 8 + t4];
            unsigned a2 = QPs[prow    ][ks * 8 + t4 + 4];
            unsigned a3 = QPs[prow + 8][ks * 8 + t4 + 4];
            #pragma unroll
            for (int ni = 0; ni < 4; ni++) {
                unsigned b0 = Vs[ks * 8 + t4    ][8 * ni + g];
                unsigned b1 = Vs[ks * 8 + t4 + 4][8 * ni + g];
                mma_tf32(o[ni], a0, a1, a2, a3, b0, b1);
            }
        }
        __syncthreads();
    }

    float inv0 = 1.0f / l0;
    float inv1 = 1.0f / l1;
    int grow = rbase + qt * 128 + prow;
    float* dst0 = &att[(size_t)grow * W + h * ROPE];
    float* dst1 = dst0 + (size_t)8 * W;
    #pragma unroll
    for (int ni = 0; ni < 4; ni++) {
        int col = 8 * ni + 2 * t4;
        *(float2*)&dst0[col] = make_float2(o[ni][0] * inv0, o[ni][1] * inv0);
        *(float2*)&dst1[col] = make_float2(o[ni][2] * inv1, o[ni][3] * inv1);
    }
}

// ---------------------------------------------------------------------------
// Launch
// ---------------------------------------------------------------------------
extern "C" void kernel_launch(void* const* d_in, const int* in_sizes, int n_in,
                              void* d_out, int out_size)
{
    const float* x   = (const float*)d_in[0];
    const float* Wq  = (const float*)d_in[1];
    const float* Wkv = (const float*)d_in[2];
    const float* Wk  = (const float*)d_in[3];
    const float* Wv  = (const float*)d_in[4];
    const float* Wo  = (const float*)d_in[5];
    const float* qg  = (const float*)d_in[6];
    const float* kg  = (const float*)d_in[7];
    float* out = (float*)d_out;

    float *pqr, *pkv, *pkvp, *pk, *pv, *patt, *pwop;
    cudaGetSymbolAddress((void**)&pqr,  g_qr);
    cudaGetSymbolAddress((void**)&pkv,  g_kv);
    cudaGetSymbolAddress((void**)&pkvp, g_kvp);
    cudaGetSymbolAddress((void**)&pk,   g_k);
    cudaGetSymbolAddress((void**)&pv,   g_v);
    cudaGetSymbolAddress((void**)&patt, g_att);
    cudaGetSymbolAddress((void**)&pwop, g_wop);

    cudaFuncSetAttribute(attn_mma_kernel,
                         cudaFuncAttributeMaxDynamicSharedMemorySize, ATTN_SMEM);

    pack_wo_kernel<<<(HH * ROPE * DD + 255) / 256, 256>>>(Wo, pwop);

    // kv = x @ Wkv, split-K x4: grid (chunk=4, mtile=64), K=256 per chunk
    gemm_tf32<3><<<dim3(KVSPLIT, ROWS / 128), 256>>>(
        ROWS, LAT, DD / KVSPLIT, DD, x, Wkv, pkvp, nullptr);
    kv_reduce_kernel<<<(ROWS * LAT / 4 + 255) / 256, 256>>>(pkvp, pkv);

    // q = rmsnorm(x @ Wq) fused -> qr (8192 x 512)
    gemm_tf32<2><<<dim3(DD / 128, ROWS / 128), 256>>>(ROWS, DD, DD, DD, x, Wq, pqr, qg);

    // k = rmsnorm(kv @ Wk) fused ; v = kv @ Wv   (8192,512,128)
    gemm_tf32<1><<<dim3((HH * ROPE) / 128, ROWS / 128), 256>>>(
        ROWS, HH * ROPE, LAT, LAT, pkv, Wk, pk, kg);
    gemm_tf32<0><<<dim3((HH * ROPE) / 128, ROWS / 128), 256>>>(
        ROWS, HH * ROPE, LAT, LAT, pkv, Wv, pv, nullptr);

    // tensor-core flash attention
    attn_mma_kernel<<<dim3(TT / 128, BB * HH), 256, ATTN_SMEM>>>(pqr, pk, pv, patt);

    // out = att @ WoP  (8192,1024,512)
    gemm_tf32<0><<<dim3(DD / 128, ROWS / 128), 256>>>(
        ROWS, DD, HH * ROPE, HH * ROPE, patt, pwop, out, nullptr);
}

// round 10
// speedup vs baseline: 3.3550x; 1.0547x over previous
#include <cuda_runtime.h>
#include <cuda_bf16.h>
#include <math.h>

// Problem constants
#define BB   4
#define TT   2048
#define DD   1024
#define HH   16
#define HD   64
#define LAT  128
#define ROPE 32
#define ROWS (BB*TT)          // 8192
#define EPSV 1e-6f
#define KVSPLIT 4

// Scratch
__device__ float g_qr [ROWS * HH * ROPE];
__device__ float g_kv [ROWS * LAT];
__device__ float g_kvp[KVSPLIT * ROWS * LAT];
__device__ float g_k  [ROWS * HH * ROPE];
__device__ float g_v  [ROWS * HH * ROPE];
__device__ float g_att[ROWS * HH * ROPE];
__device__ float g_wop[HH * ROPE * DD];

// ---------------------------------------------------------------------------
// fp32 -> tf32 bits, round-to-nearest
// ---------------------------------------------------------------------------
__device__ __forceinline__ unsigned f2tf(float f) {
    unsigned u;
    asm("cvt.rna.tf32.f32 %0, %1;" : "=r"(u) : "f"(f));
    return u;
}

__device__ __forceinline__ void mma_tf32(
    float* c, unsigned a0, unsigned a1, unsigned a2, unsigned a3,
    unsigned b0, unsigned b1)
{
    asm volatile(
        "mma.sync.aligned.m16n8k8.row.col.f32.tf32.tf32.f32 "
        "{%0,%1,%2,%3}, {%4,%5,%6,%7}, {%8,%9}, {%0,%1,%2,%3};"
        : "+f"(c[0]), "+f"(c[1]), "+f"(c[2]), "+f"(c[3])
        : "r"(a0), "r"(a1), "r"(a2), "r"(a3), "r"(b0), "r"(b1));
}

// A-tile column permutation: k and k+4 adjacent -> a-fragment LDS.64
__device__ __forceinline__ int apos(int c) {
    return ((c & 3) << 1) | ((c >> 2) & 1) | (c & 8);
}

// ---------------------------------------------------------------------------
// TF32 tensor-core GEMM (unchanged from R9).
// MODE 0 plain / 1 fused K-RMSNorm / 2 fused Q-RMSNorm / 3 split-K partials
// ---------------------------------------------------------------------------
template<int MODE>
__global__ __launch_bounds__(256) void gemm_tf32(
    int M, int N, int K, int lda,
    const float* __restrict__ A, const float* __restrict__ B,
    float* __restrict__ C, const float* __restrict__ gvec)
{
    __shared__ unsigned As[2][128][24];
    __shared__ unsigned Bs[2][16][136];
    __shared__ float ssbuf[128][4];

    const int tid  = threadIdx.x;
    const int lane = tid & 31;
    const int warp = tid >> 5;
    const int g    = lane >> 2;
    const int t4   = lane & 3;
    const int wr   = warp >> 2;
    const int wc   = warp & 3;

    const int bM = blockIdx.y * 128;
    const int bN = (MODE == 3) ? 0 : blockIdx.x * 128;

    const float* Ap = A;
    const float* Bp = B;
    float*       Cp = C;
    if (MODE == 3) {
        Ap += (size_t)blockIdx.x * K;
        Bp += (size_t)blockIdx.x * K * N;
        Cp += (size_t)blockIdx.x * M * N;
    }

    const int aRow = tid >> 2;
    const int aCol = (tid & 3) * 4;
    const int bRow = tid >> 5;
    const int bCol = (tid & 31) * 4;

    const int ap0 = apos(aCol + 0), ap1 = apos(aCol + 1);
    const int ap2 = apos(aCol + 2), ap3 = apos(aCol + 3);

    float acc[4][4][4];
    #pragma unroll
    for (int i = 0; i < 4; i++)
        #pragma unroll
        for (int j = 0; j < 4; j++)
            #pragma unroll
            for (int c = 0; c < 4; c++) acc[i][j][c] = 0.f;

    const float* Ab = Ap + (size_t)bM * lda;
    const float* Bb = Bp + bN;

    float4 ra0, ra1, rb0, rb1;

    ra0 = *(const float4*)&Ab[(size_t)aRow * lda + aCol];
    ra1 = *(const float4*)&Ab[(size_t)(aRow + 64) * lda + aCol];
    rb0 = *(const float4*)&Bb[(size_t)bRow * N + bCol];
    rb1 = *(const float4*)&Bb[(size_t)(bRow + 8) * N + bCol];
    {
        As[0][aRow][ap0] = f2tf(ra0.x); As[0][aRow][ap1] = f2tf(ra0.y);
        As[0][aRow][ap2] = f2tf(ra0.z); As[0][aRow][ap3] = f2tf(ra0.w);
        As[0][aRow+64][ap0] = f2tf(ra1.x); As[0][aRow+64][ap1] = f2tf(ra1.y);
        As[0][aRow+64][ap2] = f2tf(ra1.z); As[0][aRow+64][ap3] = f2tf(ra1.w);
        uint4 u0 = make_uint4(f2tf(rb0.x), f2tf(rb0.y), f2tf(rb0.z), f2tf(rb0.w));
        uint4 u1 = make_uint4(f2tf(rb1.x), f2tf(rb1.y), f2tf(rb1.z), f2tf(rb1.w));
        *(uint4*)&Bs[0][bRow][bCol]     = u0;
        *(uint4*)&Bs[0][bRow + 8][bCol] = u1;
    }
    __syncthreads();

    const int nIter = K >> 4;
    for (int it = 0; it < nIter; it++) {
        const int p = it & 1;
        if (it + 1 < nIter) {
            int k0 = (it + 1) << 4;
            ra0 = *(const float4*)&Ab[(size_t)aRow * lda + k0 + aCol];
            ra1 = *(const float4*)&Ab[(size_t)(aRow + 64) * lda + k0 + aCol];
            rb0 = *(const float4*)&Bb[(size_t)(k0 + bRow) * N + bCol];
            rb1 = *(const float4*)&Bb[(size_t)(k0 + bRow + 8) * N + bCol];
        }

        #pragma unroll
        for (int kb = 0; kb < 2; kb++) {
            const int kk = kb * 8;
            unsigned a[4][4], b[4][2];
            #pragma unroll
            for (int mi = 0; mi < 4; mi++) {
                int row = wr * 64 + mi * 16 + g;
                uint2 uA0 = *(const uint2*)&As[p][row    ][kk + 2 * t4];
                uint2 uA1 = *(const uint2*)&As[p][row + 8][kk + 2 * t4];
                a[mi][0] = uA0.x; a[mi][1] = uA1.x;
                a[mi][2] = uA0.y; a[mi][3] = uA1.y;
            }
            #pragma unroll
            for (int ni = 0; ni < 4; ni++) {
                int col = wc * 32 + ni * 8 + g;
                b[ni][0] = Bs[p][kk + t4    ][col];
                b[ni][1] = Bs[p][kk + t4 + 4][col];
            }
            #pragma unroll
            for (int mi = 0; mi < 4; mi++)
                #pragma unroll
                for (int ni = 0; ni < 4; ni++)
                    mma_tf32(acc[mi][ni], a[mi][0], a[mi][1], a[mi][2], a[mi][3],
                             b[ni][0], b[ni][1]);
        }

        if (it + 1 < nIter) {
            const int q = p ^ 1;
            As[q][aRow][ap0] = f2tf(ra0.x); As[q][aRow][ap1] = f2tf(ra0.y);
            As[q][aRow][ap2] = f2tf(ra0.z); As[q][aRow][ap3] = f2tf(ra0.w);
            As[q][aRow+64][ap0] = f2tf(ra1.x); As[q][aRow+64][ap1] = f2tf(ra1.y);
            As[q][aRow+64][ap2] = f2tf(ra1.z); As[q][aRow+64][ap3] = f2tf(ra1.w);
            uint4 u0 = make_uint4(f2tf(rb0.x), f2tf(rb0.y), f2tf(rb0.z), f2tf(rb0.w));
            uint4 u1 = make_uint4(f2tf(rb1.x), f2tf(rb1.y), f2tf(rb1.z), f2tf(rb1.w));
            *(uint4*)&Bs[q][bRow][bCol]     = u0;
            *(uint4*)&Bs[q][bRow + 8][bCol] = u1;
        }
        __syncthreads();
    }

    if (MODE == 0 || MODE == 3) {
        #pragma unroll
        for (int mi = 0; mi < 4; mi++) {
            #pragma unroll
            for (int ni = 0; ni < 4; ni++) {
                int row = bM + wr * 64 + mi * 16 + g;
                int col = bN + wc * 32 + ni * 8 + 2 * t4;
                *(float2*)&Cp[(size_t)row * N + col] =
                    make_float2(acc[mi][ni][0], acc[mi][ni][1]);
                *(float2*)&Cp[(size_t)(row + 8) * N + col] =
                    make_float2(acc[mi][ni][2], acc[mi][ni][3]);
            }
        }
    } else if (MODE == 1) {
        #pragma unroll
        for (int mi = 0; mi < 4; mi++) {
            float ss0 = 0.f, ss1 = 0.f;
            #pragma unroll
            for (int ni = 0; ni < 4; ni++) {
                ss0 += acc[mi][ni][0]*acc[mi][ni][0] + acc[mi][ni][1]*acc[mi][ni][1];
                ss1 += acc[mi][ni][2]*acc[mi][ni][2] + acc[mi][ni][3]*acc[mi][ni][3];
            }
            ss0 += __shfl_xor_sync(0xffffffffu, ss0, 1);
            ss0 += __shfl_xor_sync(0xffffffffu, ss0, 2);
            ss1 += __shfl_xor_sync(0xffffffffu, ss1, 1);
            ss1 += __shfl_xor_sync(0xffffffffu, ss1, 2);
            float rinv0 = rsqrtf(ss0 * (1.0f / ROPE) + EPSV);
            float rinv1 = rsqrtf(ss1 * (1.0f / ROPE) + EPSV);
            int row = bM + wr * 64 + mi * 16 + g;
            #pragma unroll
            for (int ni = 0; ni < 4; ni++) {
                int d   = ni * 8 + 2 * t4;
                int col = bN + wc * 32 + d;
                float g0 = gvec[d], g1 = gvec[d + 1];
                *(float2*)&Cp[(size_t)row * N + col] =
                    make_float2(acc[mi][ni][0] * rinv0 * g0,
                                acc[mi][ni][1] * rinv0 * g1);
                *(float2*)&Cp[(size_t)(row + 8) * N + col] =
                    make_float2(acc[mi][ni][2] * rinv1 * g0,
                                acc[mi][ni][3] * rinv1 * g1);
            }
        }
    } else {
        #pragma unroll
        for (int mi = 0; mi < 4; mi++) {
            float ss0 = 0.f, ss1 = 0.f;
            #pragma unroll
            for (int ni = 0; ni < 4; ni++) {
                ss0 += acc[mi][ni][0]*acc[mi][ni][0] + acc[mi][ni][1]*acc[mi][ni][1];
                ss1 += acc[mi][ni][2]*acc[mi][ni][2] + acc[mi][ni][3]*acc[mi][ni][3];
            }
            ss0 += __shfl_xor_sync(0xffffffffu, ss0, 1);
            ss0 += __shfl_xor_sync(0xffffffffu, ss0, 2);
            ss1 += __shfl_xor_sync(0xffffffffu, ss1, 1);
            ss1 += __shfl_xor_sync(0xffffffffu, ss1, 2);
            if (t4 == 0) {
                int lr = wr * 64 + mi * 16 + g;
                ssbuf[lr][wc]     = ss0;
                ssbuf[lr + 8][wc] = ss1;
            }
        }
        __syncthreads();
        if ((wc & 1) == 0) {
            #pragma unroll
            for (int mi = 0; mi < 4; mi++) {
                int lr = wr * 64 + mi * 16 + g;
                float t0 = ssbuf[lr][wc] + ssbuf[lr][wc ^ 1];
                float t1 = ssbuf[lr + 8][wc] + ssbuf[lr + 8][wc ^ 1];
                float rinv0 = rsqrtf(t0 * (1.0f / HD) + EPSV);
                float rinv1 = rsqrtf(t1 * (1.0f / HD) + EPSV);
                int row = bM + lr;
                #pragma unroll
                for (int ni = 0; ni < 4; ni++) {
                    int d  = ni * 8 + 2 * t4;
                    int cg = bN + wc * 32 + d;
                    int qc = (cg >> 6) * 32 + d;
                    float g0 = gvec[d], g1 = gvec[d + 1];
                    *(float2*)&Cp[(size_t)row * 512 + qc] =
                        make_float2(acc[mi][ni][0] * rinv0 * g0,
                                    acc[mi][ni][1] * rinv0 * g1);
                    *(float2*)&Cp[(size_t)(row + 8) * 512 + qc] =
                        make_float2(acc[mi][ni][2] * rinv1 * g0,
                                    acc[mi][ni][3] * rinv1 * g1);
                }
            }
        }
    }
}

// ---------------------------------------------------------------------------
// kv split-K reduce
// ---------------------------------------------------------------------------
__global__ void kv_reduce_kernel(const float* __restrict__ parts,
                                 float* __restrict__ kv)
{
    int i = (blockIdx.x * blockDim.x + threadIdx.x) * 4;
    if (i >= ROWS * LAT) return;
    const int STRIDE = ROWS * LAT;
    float4 s = *(const float4*)&parts[i];
    #pragma unroll
    for (int c = 1; c < KVSPLIT; c++) {
        float4 p = *(const float4*)&parts[c * STRIDE + i];
        s.x += p.x; s.y += p.y; s.z += p.z; s.w += p.w;
    }
    *(float4*)&kv[i] = s;
}

// ---------------------------------------------------------------------------
// Pack Wo
// ---------------------------------------------------------------------------
__global__ void pack_wo_kernel(const float* __restrict__ Wo, float* __restrict__ WoP)
{
    int idx = blockIdx.x * blockDim.x + threadIdx.x;
    if (idx >= HH * ROPE * DD) return;
    int r = idx >> 10;
    int n = idx & 1023;
    int h = r >> 5;
    int d = r & 31;
    WoP[idx] = Wo[(size_t)(h * HD + d) * DD + n];
}

// ---------------------------------------------------------------------------
// Tensor-core flash attention (causal), BQ=128, 8 warps (unchanged from R9).
// ---------------------------------------------------------------------------
#define ATTN_SMEM ((128*68 + 64*36 + 64*40) * 4)

__global__ __launch_bounds__(256) void attn_mma_kernel(
    const float* __restrict__ qr, const float* __restrict__ kk_,
    const float* __restrict__ vv, float* __restrict__ att)
{
    extern __shared__ unsigned smemraw[];
    unsigned (*QPs)[68] = (unsigned(*)[68])smemraw;
    unsigned (*Ks )[36] = (unsigned(*)[36])(smemraw + 128 * 68);
    unsigned (*Vs )[40] = (unsigned(*)[40])(smemraw + 128 * 68 + 64 * 36);

    const int qt  = (gridDim.x - 1) - blockIdx.x;
    const int bh  = blockIdx.y;
    const int b   = bh >> 4;
    const int h   = bh & 15;
    const int tid = threadIdx.x;
    const int lane = tid & 31;
    const int w    = tid >> 5;
    const int g    = lane >> 2;
    const int t4   = lane & 3;
    const int rbase = b * TT;
    const int W = HH * ROPE;

    for (int f = tid; f < 128 * 8; f += 256) {
        int row = f >> 3, c4 = (f & 7) * 4;
        float4 v = *(const float4*)&qr[(size_t)(rbase + qt * 128 + row) * W + h * ROPE + c4];
        QPs[row][c4 + 0] = __float_as_uint(v.x);
        QPs[row][c4 + 1] = __float_as_uint(v.y);
        QPs[row][c4 + 2] = __float_as_uint(v.z);
        QPs[row][c4 + 3] = __float_as_uint(v.w);
    }
    __syncthreads();

    const int prow = w * 16 + g;
    unsigned aq[4][4];
    #pragma unroll
    for (int ks = 0; ks < 4; ks++) {
        aq[ks][0] = f2tf(0.125f * __uint_as_float(QPs[prow    ][ks * 8 + t4]));
        aq[ks][1] = f2tf(0.125f * __uint_as_float(QPs[prow + 8][ks * 8 + t4]));
        aq[ks][2] = f2tf(0.125f * __uint_as_float(QPs[prow    ][ks * 8 + t4 + 4]));
        aq[ks][3] = f2tf(0.125f * __uint_as_float(QPs[prow + 8][ks * 8 + t4 + 4]));
    }

    float m0 = -INFINITY, m1 = -INFINITY, l0 = 0.f, l1 = 0.f;
    float o[4][4];
    #pragma unroll
    for (int ni = 0; ni < 4; ni++)
        #pragma unroll
        for (int c = 0; c < 4; c++) o[ni][c] = 0.f;

    const int pfRow0 = tid >> 3;
    const int pfRow1 = (tid >> 3) + 32;
    const int pfC4   = (tid & 7) * 4;

    const int nkt = 2 * qt + 2;

    float4 rk0, rk1, rv0, rv1;
    {
        size_t g0 = (size_t)(rbase + pfRow0) * W + h * ROPE + pfC4;
        size_t g1 = (size_t)(rbase + pfRow1) * W + h * ROPE + pfC4;
        rk0 = *(const float4*)&kk_[g0];
        rk1 = *(const float4*)&kk_[g1];
        rv0 = *(const float4*)&vv[g0];
        rv1 = *(const float4*)&vv[g1];
    }

    for (int kt = 0; kt < nkt; kt++) {
        Ks[pfRow0][pfC4+0] = f2tf(rk0.x); Ks[pfRow0][pfC4+1] = f2tf(rk0.y);
        Ks[pfRow0][pfC4+2] = f2tf(rk0.z); Ks[pfRow0][pfC4+3] = f2tf(rk0.w);
        Ks[pfRow1][pfC4+0] = f2tf(rk1.x); Ks[pfRow1][pfC4+1] = f2tf(rk1.y);
        Ks[pfRow1][pfC4+2] = f2tf(rk1.z); Ks[pfRow1][pfC4+3] = f2tf(rk1.w);
        Vs[pfRow0][pfC4+0] = f2tf(rv0.x); Vs[pfRow0][pfC4+1] = f2tf(rv0.y);
        Vs[pfRow0][pfC4+2] = f2tf(rv0.z); Vs[pfRow0][pfC4+3] = f2tf(rv0.w);
        Vs[pfRow1][pfC4+0] = f2tf(rv1.x); Vs[pfRow1][pfC4+1] = f2tf(rv1.y);
        Vs[pfRow1][pfC4+2] = f2tf(rv1.z); Vs[pfRow1][pfC4+3] = f2tf(rv1.w);
        __syncthreads();

        if (kt + 1 < nkt) {
            size_t g0 = (size_t)(rbase + (kt + 1) * 64 + pfRow0) * W + h * ROPE + pfC4;
            size_t g1 = (size_t)(rbase + (kt + 1) * 64 + pfRow1) * W + h * ROPE + pfC4;
            rk0 = *(const float4*)&kk_[g0];
            rk1 = *(const float4*)&kk_[g1];
            rv0 = *(const float4*)&vv[g0];
            rv1 = *(const float4*)&vv[g1];
        }

        float s[8][4];
        #pragma unroll
        for (int j = 0; j < 8; j++)
            #pragma unroll
            for (int c = 0; c < 4; c++) s[j][c] = 0.f;

        #pragma unroll
        for (int ks = 0; ks < 4; ks++) {
            #pragma unroll
            for (int j = 0; j < 8; j++) {
                unsigned b0 = Ks[8 * j + g][ks * 8 + t4];
                unsigned b1 = Ks[8 * j + g][ks * 8 + t4 + 4];
                mma_tf32(s[j], aq[ks][0], aq[ks][1], aq[ks][2], aq[ks][3], b0, b1);
            }
        }

        if (kt >= 2 * qt) {
            int off = (kt - 2 * qt) * 64;
            #pragma unroll
            for (int j = 0; j < 8; j++) {
                int cl = off + 8 * j + 2 * t4;
                if (cl     > prow    ) s[j][0] = -INFINITY;
                if (cl + 1 > prow    ) s[j][1] = -INFINITY;
                if (cl     > prow + 8) s[j][2] = -INFINITY;
                if (cl + 1 > prow + 8) s[j][3] = -INFINITY;
            }
        }

        float mx0 = m0, mx1 = m1;
        #pragma unroll
        for (int j = 0; j < 8; j++) {
            mx0 = fmaxf(mx0, fmaxf(s[j][0], s[j][1]));
            mx1 = fmaxf(mx1, fmaxf(s[j][2], s[j][3]));
        }
        mx0 = fmaxf(mx0, __shfl_xor_sync(0xffffffffu, mx0, 1));
        mx0 = fmaxf(mx0, __shfl_xor_sync(0xffffffffu, mx0, 2));
        mx1 = fmaxf(mx1, __shfl_xor_sync(0xffffffffu, mx1, 1));
        mx1 = fmaxf(mx1, __shfl_xor_sync(0xffffffffu, mx1, 2));

        float sc0 = __expf(m0 - mx0);
        float sc1 = __expf(m1 - mx1);
        m0 = mx0; m1 = mx1;

        float ls0 = 0.f, ls1 = 0.f;
        #pragma unroll
        for (int j = 0; j < 8; j++) {
            float p0 = __expf(s[j][0] - m0);
            float p1 = __expf(s[j][1] - m0);
            float p2 = __expf(s[j][2] - m1);
            float p3 = __expf(s[j][3] - m1);
            ls0 += p0 + p1;
            ls1 += p2 + p3;
            QPs[prow    ][8 * j + 2 * t4    ] = f2tf(p0);
            QPs[prow    ][8 * j + 2 * t4 + 1] = f2tf(p1);
            QPs[prow + 8][8 * j + 2 * t4    ] = f2tf(p2);
            QPs[prow + 8][8 * j + 2 * t4 + 1] = f2tf(p3);
        }
        ls0 += __shfl_xor_sync(0xffffffffu, ls0, 1);
        ls0 += __shfl_xor_sync(0xffffffffu, ls0, 2);
        ls1 += __shfl_xor_sync(0xffffffffu, ls1, 1);
        ls1 += __shfl_xor_sync(0xffffffffu, ls1, 2);
        l0 = l0 * sc0 + ls0;
        l1 = l1 * sc1 + ls1;

        #pragma unroll
        for (int ni = 0; ni < 4; ni++) {
            o[ni][0] *= sc0; o[ni][1] *= sc0;
            o[ni][2] *= sc1; o[ni][3] *= sc1;
        }
        __syncwarp();

        #pragma unroll
        for (int ks = 0; ks < 8; ks++) {
            unsigned a0 = QPs[prow    ][ks * 8 + t4];
            unsigned a1 = QPs[prow + 8][ks * 8 + t4];
            unsigned a2 = QPs[prow    ][ks * 8 + t4 + 4];
            unsigned a3 = QPs[prow + 8][ks * 8 + t4 + 4];
            #pragma unroll
            for (int ni = 0; ni < 4; ni++) {
                unsigned b0 = Vs[ks * 8 + t4    ][8 * ni + g];
                unsigned b1 = Vs[ks * 8 + t4 + 4][8 * ni + g];
                mma_tf32(o[ni], a0, a1, a2, a3, b0, b1);
            }
        }
        __syncthreads();
    }

    float inv0 = 1.0f / l0;
    float inv1 = 1.0f / l1;
    int grow = rbase + qt * 128 + prow;
    float* dst0 = &att[(size_t)grow * W + h * ROPE];
    float* dst1 = dst0 + (size_t)8 * W;
    #pragma unroll
    for (int ni = 0; ni < 4; ni++) {
        int col = 8 * ni + 2 * t4;
        *(float2*)&dst0[col] = make_float2(o[ni][0] * inv0, o[ni][1] * inv0);
        *(float2*)&dst1[col] = make_float2(o[ni][2] * inv1, o[ni][3] * inv1);
    }
}

// ---------------------------------------------------------------------------
// Launch: two parallel branches captured into the graph via event fork/join.
//   branch A (null stream): pack_wo -> xWq
//   branch B (s2):          kv-split -> reduce -> k -> v
//   join -> attention -> out@Wo
// ---------------------------------------------------------------------------
extern "C" void kernel_launch(void* const* d_in, const int* in_sizes, int n_in,
                              void* d_out, int out_size)
{
    const float* x   = (const float*)d_in[0];
    const float* Wq  = (const float*)d_in[1];
    const float* Wkv = (const float*)d_in[2];
    const float* Wk  = (const float*)d_in[3];
    const float* Wv  = (const float*)d_in[4];
    const float* Wo  = (const float*)d_in[5];
    const float* qg  = (const float*)d_in[6];
    const float* kg  = (const float*)d_in[7];
    float* out = (float*)d_out;

    float *pqr, *pkv, *pkvp, *pk, *pv, *patt, *pwop;
    cudaGetSymbolAddress((void**)&pqr,  g_qr);
    cudaGetSymbolAddress((void**)&pkv,  g_kv);
    cudaGetSymbolAddress((void**)&pkvp, g_kvp);
    cudaGetSymbolAddress((void**)&pk,   g_k);
    cudaGetSymbolAddress((void**)&pv,   g_v);
    cudaGetSymbolAddress((void**)&patt, g_att);
    cudaGetSymbolAddress((void**)&pwop, g_wop);

    // lazily-created side stream + fork/join events (not device allocations)
    static cudaStream_t s2 = nullptr;
    static cudaEvent_t  evFork = nullptr, evJoin = nullptr;
    if (s2 == nullptr) {
        cudaStreamCreateWithFlags(&s2, cudaStreamNonBlocking);
        cudaEventCreateWithFlags(&evFork, cudaEventDisableTiming);
        cudaEventCreateWithFlags(&evJoin, cudaEventDisableTiming);
        cudaFuncSetAttribute(attn_mma_kernel,
                             cudaFuncAttributeMaxDynamicSharedMemorySize, ATTN_SMEM);
    }

    // ---- fork ----
    cudaEventRecord(evFork, 0);              // on capture-origin (null) stream
    cudaStreamWaitEvent(s2, evFork, 0);

    // branch B on s2: kv chain (independent of xWq)
    gemm_tf32<3><<<dim3(KVSPLIT, ROWS / 128), 256, 0, s2>>>(
        ROWS, LAT, DD / KVSPLIT, DD, x, Wkv, pkvp, nullptr);
    kv_reduce_kernel<<<(ROWS * LAT / 4 + 255) / 256, 256, 0, s2>>>(pkvp, pkv);
    gemm_tf32<1><<<dim3((HH * ROPE) / 128, ROWS / 128), 256, 0, s2>>>(
        ROWS, HH * ROPE, LAT, LAT, pkv, Wk, pk, kg);
    gemm_tf32<0><<<dim3((HH * ROPE) / 128, ROWS / 128), 256, 0, s2>>>(
        ROWS, HH * ROPE, LAT, LAT, pkv, Wv, pv, nullptr);
    cudaEventRecord(evJoin, s2);

    // branch A on null stream: Wo pack + the long-pole xWq GEMM
    pack_wo_kernel<<<(HH * ROPE * DD + 255) / 256, 256>>>(Wo, pwop);
    gemm_tf32<2><<<dim3(DD / 128, ROWS / 128), 256>>>(ROWS, DD, DD, DD, x, Wq, pqr, qg);

    // ---- join ----
    cudaStreamWaitEvent(0, evJoin, 0);

    // attention (needs qr, k, v)
    attn_mma_kernel<<<dim3(TT / 128, BB * HH), 256, ATTN_SMEM>>>(pqr, pk, pv, patt);

    // out = att @ WoP
    gemm_tf32<0><<<dim3(DD / 128, ROWS / 128), 256>>>(
        ROWS, DD, HH * ROPE, HH * ROPE, patt, pwop, out, nullptr);
}